// round 7
// baseline (speedup 1.0000x reference)
#include <cuda_runtime.h>
#include <cuda_bf16.h>
#include <math.h>
#include <stdint.h>

// ---------------- problem constants ----------------
#define NB   32
#define NS   128
#define NDIM 1024
#define NH   16
#define HD   64
#define NL   6
#define NV   18
#define NTOK 256
#define NHID 4096
#define NEGV (-10000.0f)

#define MQ (NB * NTOK)     // 8192
#define MC (NB * NS)       // 4096

// ---------------- weight pool layout (bf16, transposed [N,K]) ----------------
#define OFF_MOD 0ULL
#define OFF_SAQ 6291456ULL
#define OFF_SAK 7340032ULL
#define OFF_SAV 8388608ULL
#define OFF_SAP 9437184ULL
#define OFF_CAQ 10485760ULL
#define OFF_CAK 11534336ULL
#define OFF_CAV 12582912ULL
#define OFF_CAP 13631488ULL
#define OFF_AL0 14680064ULL
#define OFF_AL1 15728640ULL
#define OFF_FC1 16777216ULL
#define OFF_FC2 20971520ULL
#define WPL     25165824ULL
#define WTOT    (6ULL * WPL)

// ---------------- scratch (device globals) ----------------
__device__ float g_x    [(size_t)MQ * NDIM];
__device__ float g_x2   [(size_t)MQ * NDIM];
__device__ float g_qh   [(size_t)MQ * NDIM];
__device__ float g_kh   [(size_t)MQ * NDIM];
__device__ float g_vh   [(size_t)MQ * NDIM];
__device__ float g_q2b  [(size_t)MQ * NDIM];
__device__ float g_alpha[(size_t)MQ * NDIM];
__device__ float g_mod  [(size_t)MC * 6 * NDIM];
__device__ float g_lncpe[(size_t)MC * NDIM];
__device__ float g_lnc  [(size_t)MC * NDIM];

__device__ __nv_bfloat16 g_whi[WTOT];
__device__ __nv_bfloat16 g_wlo[WTOT];
__device__ __nv_bfloat16 g_xh [(size_t)MQ * NDIM];
__device__ __nv_bfloat16 g_xl [(size_t)MQ * NDIM];
__device__ __nv_bfloat16 g_ath[(size_t)MQ * NDIM];
__device__ __nv_bfloat16 g_atl[(size_t)MQ * NDIM];
__device__ __nv_bfloat16 g_q2h[(size_t)MQ * NDIM];
__device__ __nv_bfloat16 g_q2l[(size_t)MQ * NDIM];
__device__ __nv_bfloat16 g_kih[(size_t)MC * NDIM];
__device__ __nv_bfloat16 g_kil[(size_t)MC * NDIM];
__device__ __nv_bfloat16 g_vih[(size_t)MC * NDIM];
__device__ __nv_bfloat16 g_vil[(size_t)MC * NDIM];
__device__ __nv_bfloat16 g_sch[(size_t)MC * NDIM];
__device__ __nv_bfloat16 g_scl[(size_t)MC * NDIM];
__device__ __nv_bfloat16 g_hbh[(size_t)MQ * NHID];
__device__ __nv_bfloat16 g_hbl[(size_t)MQ * NHID];

// ================= portable PTX helpers =================
__device__ __forceinline__ uint32_t smem_to_u32(const void* p) {
    uint32_t a;
    asm("{ .reg .u64 t; cvta.to.shared.u64 t, %1; cvt.u32.u64 %0, t; }" : "=r"(a) : "l"(p));
    return a;
}
__device__ __forceinline__ void cpa16(uint32_t dst, const void* src) {
    asm volatile("cp.async.cg.shared.global [%0], [%1], 16;" :: "r"(dst), "l"(src) : "memory");
}
#define CP_COMMIT() asm volatile("cp.async.commit_group;" ::: "memory")
template <int N> __device__ __forceinline__ void cp_wait() {
    asm volatile("cp.async.wait_group %0;" :: "n"(N) : "memory");
}
__device__ __forceinline__ void ldsm4(uint32_t* r, uint32_t addr) {
    asm volatile("ldmatrix.sync.aligned.m8n8.x4.shared.b16 {%0,%1,%2,%3}, [%4];"
                 : "=r"(r[0]), "=r"(r[1]), "=r"(r[2]), "=r"(r[3]) : "r"(addr));
}
__device__ __forceinline__ void mma16816(float* c, const uint32_t* a, const uint32_t* b) {
    asm volatile("mma.sync.aligned.m16n8k16.row.col.f32.bf16.bf16.f32 "
                 "{%0,%1,%2,%3}, {%4,%5,%6,%7}, {%8,%9}, {%0,%1,%2,%3};"
                 : "+f"(c[0]), "+f"(c[1]), "+f"(c[2]), "+f"(c[3])
                 : "r"(a[0]), "r"(a[1]), "r"(a[2]), "r"(a[3]), "r"(b[0]), "r"(b[1]));
}

// smem geometry: 4 tiles (Ah,Al,Bh,Bl) of 128 rows x 32 bf16, row stride 80B
#define TILE_BYTES 10240            // 128 * 80
#define STAGE_BYTES 40960           // 4 tiles
#define NSTAGE 4
#define GEMM_SMEM (NSTAGE * STAGE_BYTES)   // 163840

// ---------------- hi/lo split store helpers ----------------
__device__ __forceinline__ void split_store4(__nv_bfloat16* hp, __nv_bfloat16* lp,
                                             size_t idx, float4 v) {
    __nv_bfloat16 h[4], lo[4];
    float f[4] = {v.x, v.y, v.z, v.w};
    #pragma unroll
    for (int u = 0; u < 4; u++) {
        h[u]  = __float2bfloat16(f[u]);
        lo[u] = __float2bfloat16(f[u] - __bfloat162float(h[u]));
    }
    *reinterpret_cast<uint2*>(hp + idx) = *reinterpret_cast<uint2*>(h);
    *reinterpret_cast<uint2*>(lp + idx) = *reinterpret_cast<uint2*>(lo);
}
__device__ __forceinline__ void split_store2(__nv_bfloat16* hp, __nv_bfloat16* lp,
                                             size_t idx, float v0, float v1) {
    __nv_bfloat16 h[2], lo[2];
    h[0] = __float2bfloat16(v0); lo[0] = __float2bfloat16(v0 - __bfloat162float(h[0]));
    h[1] = __float2bfloat16(v1); lo[1] = __float2bfloat16(v1 - __bfloat162float(h[1]));
    *reinterpret_cast<uint32_t*>(hp + idx) = *reinterpret_cast<uint32_t*>(h);
    *reinterpret_cast<uint32_t*>(lp + idx) = *reinterpret_cast<uint32_t*>(lo);
}

// ================= mma.sync split-bf16 GEMM (4-stage cp.async pipeline) =================
__global__ __launch_bounds__(256, 1) void mm_gemm_kernel(
    const __nv_bfloat16* __restrict__ Ah, const __nv_bfloat16* __restrict__ Al,
    const __nv_bfloat16* __restrict__ Bh, const __nv_bfloat16* __restrict__ Bl,
    const float* __restrict__ bias, const float* __restrict__ res,
    float* __restrict__ C, __nv_bfloat16* __restrict__ Ch, __nv_bfloat16* __restrict__ Cl,
    int M, int N, int K, int act)
{
    extern __shared__ char smem[];
    const uint32_t sb = smem_to_u32(smem);
    const int tid  = threadIdx.x;
    const int lane = tid & 31;
    const int wid  = tid >> 5;
    const int wm   = wid & 3;     // warp m index (0..3), 32 rows each
    const int wn   = wid >> 2;    // warp n index (0..1), 64 cols each
    const int bm = blockIdx.y * 128;
    const int bn = blockIdx.x * 128;

    float acc[2][8][4];
    #pragma unroll
    for (int mt = 0; mt < 2; mt++)
        #pragma unroll
        for (int nt = 0; nt < 8; nt++)
            #pragma unroll
            for (int u = 0; u < 4; u++) acc[mt][nt][u] = 0.0f;

    uint32_t a_off[2];
    #pragma unroll
    for (int mt = 0; mt < 2; mt++)
        a_off[mt] = (uint32_t)((wm * 32 + mt * 16 + (lane & 15)) * 80 + ((lane >> 4) << 4));
    const int g = lane >> 3;
    uint32_t b_off[4];
    #pragma unroll
    for (int p = 0; p < 4; p++)
        b_off[p] = (uint32_t)((wn * 64 + p * 16 + ((g >> 1) << 3) + (lane & 7)) * 80
                              + ((g & 1) << 4));

    const int NIT = K >> 5;       // BK = 32

    auto load_stage = [&](int it, int s) {
        const int k0 = it << 5;
        const uint32_t sbase = sb + (uint32_t)s * STAGE_BYTES;
        const __nv_bfloat16* gsrc[4] = {
            Ah + (size_t)bm * K + k0, Al + (size_t)bm * K + k0,
            Bh + (size_t)bn * K + k0, Bl + (size_t)bn * K + k0 };
        #pragma unroll
        for (int t = 0; t < 4; t++) {
            #pragma unroll
            for (int u = 0; u < 2; u++) {
                const int q   = tid + u * 256;
                const int row = q >> 2, c = q & 3;
                cpa16(sbase + (uint32_t)t * TILE_BYTES + row * 80 + c * 16,
                      gsrc[t] + (size_t)row * K + c * 8);
            }
        }
        CP_COMMIT();
    };

    // prologue: fill NSTAGE-1 stages
    #pragma unroll
    for (int p = 0; p < NSTAGE - 1; p++) load_stage(p, p);

    for (int it = 0; it < NIT; it++) {
        const int s = it & (NSTAGE - 1);
        if (it + NSTAGE - 1 < NIT) {
            cp_wait<NSTAGE - 2>();          // stage it ready
            __syncthreads();                // all warps past compute(it-1)
            load_stage(it + NSTAGE - 1, (it + NSTAGE - 1) & (NSTAGE - 1));
        } else if (it + NSTAGE - 1 == NIT) {
            cp_wait<0>();
            __syncthreads();
        }

        const uint32_t sbase = sb + (uint32_t)s * STAGE_BYTES;
        #pragma unroll
        for (int ks = 0; ks < 2; ks++) {
            const uint32_t kb = (uint32_t)(ks << 5);
            uint32_t fah[2][4], fal[2][4], fbh[8][2], fbl[8][2];
            #pragma unroll
            for (int mt = 0; mt < 2; mt++) {
                ldsm4(fah[mt], sbase + a_off[mt] + kb);
                ldsm4(fal[mt], sbase + TILE_BYTES + a_off[mt] + kb);
            }
            #pragma unroll
            for (int p = 0; p < 4; p++) {
                uint32_t t4[4];
                ldsm4(t4, sbase + 2 * TILE_BYTES + b_off[p] + kb);
                fbh[2 * p][0] = t4[0]; fbh[2 * p][1] = t4[1];
                fbh[2 * p + 1][0] = t4[2]; fbh[2 * p + 1][1] = t4[3];
                ldsm4(t4, sbase + 3 * TILE_BYTES + b_off[p] + kb);
                fbl[2 * p][0] = t4[0]; fbl[2 * p][1] = t4[1];
                fbl[2 * p + 1][0] = t4[2]; fbl[2 * p + 1][1] = t4[3];
            }
            #pragma unroll
            for (int mt = 0; mt < 2; mt++)
                #pragma unroll
                for (int nt = 0; nt < 8; nt++) {
                    mma16816(acc[mt][nt], fah[mt], fbh[nt]);
                    mma16816(acc[mt][nt], fah[mt], fbl[nt]);
                    mma16816(acc[mt][nt], fal[mt], fbh[nt]);
                }
        }
    }

    // epilogue
    const int cn0 = (lane & 3) << 1;
    #pragma unroll
    for (int mt = 0; mt < 2; mt++) {
        #pragma unroll
        for (int nt = 0; nt < 8; nt++) {
            const int gn = bn + wn * 64 + nt * 8 + cn0;
            #pragma unroll
            for (int half = 0; half < 2; half++) {
                const int gm = bm + wm * 32 + mt * 16 + (lane >> 2) + half * 8;
                float v0 = acc[mt][nt][half * 2];
                float v1 = acc[mt][nt][half * 2 + 1];
                if (bias) { v0 += bias[gn]; v1 += bias[gn + 1]; }
                if (act) {
                    v0 = 0.5f * v0 * (1.0f + erff(v0 * 0.70710678118654752f));
                    v1 = 0.5f * v1 * (1.0f + erff(v1 * 0.70710678118654752f));
                }
                const size_t oidx = (size_t)gm * N + gn;
                if (res) { v0 += res[oidx]; v1 += res[oidx + 1]; }
                if (C) { C[oidx] = v0; C[oidx + 1] = v1; }
                if (Ch) split_store2(Ch, Cl, oidx, v0, v1);
            }
        }
    }
}

static inline void tcg(const __nv_bfloat16* Ah, const __nv_bfloat16* Al,
                       const __nv_bfloat16* Bh, const __nv_bfloat16* Bl,
                       const float* bias, const float* res, float* C,
                       __nv_bfloat16* Ch, __nv_bfloat16* Cl,
                       int M, int N, int K, int act) {
    dim3 grid(N / 128, M / 128);
    mm_gemm_kernel<<<grid, 256, GEMM_SMEM>>>(Ah, Al, Bh, Bl, bias, res, C, Ch, Cl, M, N, K, act);
}

// ================= batched weight prep: W[K,N] fp32 -> Wt hi/lo [N,K] bf16 =================
__global__ void wprep_kernel(const float* __restrict__ W, __nv_bfloat16* __restrict__ H,
                             __nv_bfloat16* __restrict__ Lo, int K, int N,
                             size_t src_stride, size_t dst_stride) {
    __shared__ float t[32][33];
    const size_t lyr = blockIdx.z;
    W  += lyr * src_stride;
    H  += lyr * dst_stride;
    Lo += lyr * dst_stride;
    const int bx = blockIdx.x * 32, by = blockIdx.y * 32;
    const int tx = threadIdx.x, ty = threadIdx.y;
    #pragma unroll
    for (int i = 0; i < 32; i += 8)
        t[ty + i][tx] = W[(size_t)(by + ty + i) * N + bx + tx];
    __syncthreads();
    #pragma unroll
    for (int i = 0; i < 32; i += 8) {
        const int n = bx + ty + i, k = by + tx;
        const float v = t[tx][ty + i];
        const __nv_bfloat16 h = __float2bfloat16(v);
        H [(size_t)n * K + k] = h;
        Lo[(size_t)n * K + k] = __float2bfloat16(v - __bfloat162float(h));
    }
}
static inline void wprep(const float* W, __nv_bfloat16* H, __nv_bfloat16* L, int K, int N,
                         size_t sstr, size_t dstr) {
    wprep_kernel<<<dim3(N / 32, K / 32, NL), dim3(32, 8)>>>(W, H, L, K, N, sstr, dstr);
}

// ---------------- block reduction ----------------
__device__ __forceinline__ float block_sum_256(float v) {
    __shared__ float sbuf[8];
    int tid = threadIdx.x;
    #pragma unroll
    for (int o = 16; o > 0; o >>= 1) v += __shfl_xor_sync(0xffffffffu, v, o);
    if ((tid & 31) == 0) sbuf[tid >> 5] = v;
    __syncthreads();
    float r = 0.0f;
    if (tid < 32) {
        r = (tid < 8) ? sbuf[tid] : 0.0f;
        #pragma unroll
        for (int o = 4; o > 0; o >>= 1) r += __shfl_xor_sync(0xffffffffu, r, o);
        if (tid == 0) sbuf[0] = r;
    }
    __syncthreads();
    r = sbuf[0];
    __syncthreads();
    return r;
}

// ---------------- fp32 SGEMM (head only, N=18) ----------------
__global__ __launch_bounds__(256) void sgemm_kernel(
    const float* __restrict__ A, const float* __restrict__ B,
    const float* __restrict__ bias, float* __restrict__ C, int M, int N, int K)
{
    __shared__ float As[16][128];
    __shared__ float Bs[16][128];
    const int bm = blockIdx.y * 128, bn = blockIdx.x * 128;
    const int tid = threadIdx.x;
    const int ty = tid >> 4, tx = tid & 15;
    const int arow = tid >> 2, acol = (tid & 3) << 2;
    const int brow = tid >> 5, bcol = (tid & 31) << 2;
    float acc[8][8];
    #pragma unroll
    for (int i = 0; i < 8; i++)
        #pragma unroll
        for (int j = 0; j < 8; j++) acc[i][j] = 0.0f;
    for (int k0 = 0; k0 < K; k0 += 16) {
        #pragma unroll
        for (int r = 0; r < 2; r++) {
            int row = arow + r * 64, gm = bm + row;
            float4 v = make_float4(0.f, 0.f, 0.f, 0.f);
            if (gm < M) v = *(const float4*)(A + (size_t)gm * K + k0 + acol);
            As[acol][row] = v.x; As[acol + 1][row] = v.y;
            As[acol + 2][row] = v.z; As[acol + 3][row] = v.w;
        }
        #pragma unroll
        for (int r = 0; r < 2; r++) {
            int row = brow + r * 8, gk = k0 + row, gn = bn + bcol;
            float4 v = make_float4(0.f, 0.f, 0.f, 0.f);
            const float* bp = B + (size_t)gk * N + gn;
            if (gn < N)     v.x = bp[0];
            if (gn + 1 < N) v.y = bp[1];
            if (gn + 2 < N) v.z = bp[2];
            if (gn + 3 < N) v.w = bp[3];
            *(float4*)&Bs[row][bcol] = v;
        }
        __syncthreads();
        #pragma unroll
        for (int k = 0; k < 16; k++) {
            float4 a0 = *(const float4*)&As[k][ty * 8];
            float4 a1 = *(const float4*)&As[k][ty * 8 + 4];
            float4 b0 = *(const float4*)&Bs[k][tx * 8];
            float4 b1 = *(const float4*)&Bs[k][tx * 8 + 4];
            float av[8] = {a0.x, a0.y, a0.z, a0.w, a1.x, a1.y, a1.z, a1.w};
            float bv[8] = {b0.x, b0.y, b0.z, b0.w, b1.x, b1.y, b1.z, b1.w};
            #pragma unroll
            for (int i = 0; i < 8; i++)
                #pragma unroll
                for (int j = 0; j < 8; j++) acc[i][j] += av[i] * bv[j];
        }
        __syncthreads();
    }
    #pragma unroll
    for (int i = 0; i < 8; i++) {
        int m = bm + ty * 8 + i;
        if (m >= M) continue;
        #pragma unroll
        for (int j = 0; j < 8; j++) {
            int n = bn + tx * 8 + j;
            if (n < N) C[(size_t)m * N + n] = acc[i][j] + (bias ? bias[n] : 0.0f);
        }
    }
}

// ---------------- fused attention: 2 queries per thread-pair, d-split ----------------
// 256 threads = 128 units x 2. Unit u handles queries {2u, 2u+1}; thread half owns 32 dims.
template<bool SELF, int KTOK>
__global__ __launch_bounds__(256, 1) void attn_kernel(
    const float* __restrict__ Q, const float* __restrict__ K,
    const float* __restrict__ V, const int* __restrict__ pm,
    __nv_bfloat16* __restrict__ Oh, __nv_bfloat16* __restrict__ Ol)
{
    __shared__ float ks[64][64];
    __shared__ float vs[64][64];
    __shared__ float pmb[KTOK];
    const int h = blockIdx.x, b = blockIdx.y;
    const int tid  = threadIdx.x;
    const int unit = tid >> 1;
    const int half = tid & 1;
    const int dbase = half * 32;
    const unsigned pmask = 3u << (tid & 30);   // the two lanes of this unit

    if (tid < KTOK) {
        int ct = SELF ? (tid >> 1) : tid;
        pmb[tid] = (float)pm[b * NS + ct] * NEGV;
    }

    float qr[2][32], acc[2][32];
    #pragma unroll
    for (int qi = 0; qi < 2; qi++) {
        const float* qp = Q + ((size_t)(b * NTOK + unit * 2 + qi) * NDIM + h * HD + dbase);
        #pragma unroll
        for (int d = 0; d < 32; d += 4) {
            float4 t = *(const float4*)(qp + d);
            qr[qi][d] = t.x; qr[qi][d + 1] = t.y; qr[qi][d + 2] = t.z; qr[qi][d + 3] = t.w;
            acc[qi][d] = 0.f; acc[qi][d + 1] = 0.f; acc[qi][d + 2] = 0.f; acc[qi][d + 3] = 0.f;
        }
    }

    float m0 = -INFINITY, m1 = -INFINITY, l0 = 0.f, l1 = 0.f;
    const int jmax0 = SELF ? (unit * 2)     : unit;
    const int jmax1 = SELF ? (unit * 2 + 1) : unit;

    for (int c0 = 0; c0 < KTOK; c0 += 64) {
        __syncthreads();
        #pragma unroll
        for (int u = 0; u < 4; u++) {
            int lin = tid + u * 256;
            int row = lin >> 4, c4 = (lin & 15) << 2;
            size_t gidx = (size_t)(b * KTOK + c0 + row) * NDIM + h * HD + c4;
            *(float4*)&ks[row][c4] = *(const float4*)(K + gidx);
            *(float4*)&vs[row][c4] = *(const float4*)(V + gidx);
        }
        __syncthreads();
        int jend = jmax1 - c0; if (jend > 63) jend = 63;
        for (int j = 0; j <= jend; j++) {
            float d0 = 0.f, d1 = 0.f;
            #pragma unroll
            for (int d = 0; d < 32; d += 4) {
                float4 kk = *(const float4*)&ks[j][dbase + d];
                d0 += qr[0][d] * kk.x + qr[0][d + 1] * kk.y + qr[0][d + 2] * kk.z + qr[0][d + 3] * kk.w;
                d1 += qr[1][d] * kk.x + qr[1][d + 1] * kk.y + qr[1][d + 2] * kk.z + qr[1][d + 3] * kk.w;
            }
            d0 += __shfl_xor_sync(pmask, d0, 1);
            d1 += __shfl_xor_sync(pmask, d1, 1);
            const float pb = pmb[c0 + j];
            // query1 (always valid at j <= jend)
            float s1 = d1 * 0.125f + pb;
            float nm1 = fmaxf(m1, s1);
            float corr1 = __expf(m1 - nm1);
            float p1 = __expf(s1 - nm1);
            m1 = nm1; l1 = l1 * corr1 + p1;
            // query0 (one fewer valid key in self-attn)
            float p0 = 0.f, corr0 = 1.f;
            if (!SELF || (c0 + j) <= jmax0) {
                float s0 = d0 * 0.125f + pb;
                float nm0 = fmaxf(m0, s0);
                corr0 = __expf(m0 - nm0);
                p0 = __expf(s0 - nm0);
                m0 = nm0; l0 = l0 * corr0 + p0;
            }
            #pragma unroll
            for (int d = 0; d < 32; d += 4) {
                float4 vv = *(const float4*)&vs[j][dbase + d];
                acc[0][d]     = acc[0][d]     * corr0 + p0 * vv.x;
                acc[0][d + 1] = acc[0][d + 1] * corr0 + p0 * vv.y;
                acc[0][d + 2] = acc[0][d + 2] * corr0 + p0 * vv.z;
                acc[0][d + 3] = acc[0][d + 3] * corr0 + p0 * vv.w;
                acc[1][d]     = acc[1][d]     * corr1 + p1 * vv.x;
                acc[1][d + 1] = acc[1][d + 1] * corr1 + p1 * vv.y;
                acc[1][d + 2] = acc[1][d + 2] * corr1 + p1 * vv.z;
                acc[1][d + 3] = acc[1][d + 3] * corr1 + p1 * vv.w;
            }
        }
    }
    const float inv0 = 1.0f / l0, inv1 = 1.0f / l1;
    #pragma unroll
    for (int qi = 0; qi < 2; qi++) {
        const float inv = qi ? inv1 : inv0;
        const size_t off = (size_t)(b * NTOK + unit * 2 + qi) * NDIM + h * HD + dbase;
        #pragma unroll
        for (int d = 0; d < 32; d += 4)
            split_store4(Oh, Ol, off + d,
                         make_float4(acc[qi][d] * inv, acc[qi][d + 1] * inv,
                                     acc[qi][d + 2] * inv, acc[qi][d + 3] * inv));
    }
}

// ---------------- modulated LN -> fp32 x + hi/lo split ----------------
__global__ __launch_bounds__(256) void modln_kernel(
    const float* __restrict__ x, const float* __restrict__ mod,
    float* __restrict__ out, __nv_bfloat16* __restrict__ oh, __nv_bfloat16* __restrict__ ol,
    int stage)
{
    int row = blockIdx.x, tid = threadIdx.x;
    int b = row / NTOK, n = row % NTOK, ct = n >> 1;
    float4 v = ((const float4*)(x + (size_t)row * NDIM))[tid];
    float sum = block_sum_256(v.x + v.y + v.z + v.w);
    float mean = sum * (1.0f / NDIM);
    float dx = v.x - mean, dy = v.y - mean, dz = v.z - mean, dw = v.w - mean;
    float sq = block_sum_256(dx * dx + dy * dy + dz * dz + dw * dw);
    float r = rsqrtf(sq * (1.0f / NDIM) + 1e-6f);
    const float* mp = mod + (size_t)(b * NS + ct) * (6 * NDIM) + (size_t)(2 * stage) * NDIM;
    float4 s4  = *(const float4*)(mp + tid * 4);
    float4 sh4 = *(const float4*)(mp + NDIM + tid * 4);
    float4 o;
    o.x = dx * r * (1.0f + s4.x) + sh4.x;
    o.y = dy * r * (1.0f + s4.y) + sh4.y;
    o.z = dz * r * (1.0f + s4.z) + sh4.z;
    o.w = dw * r * (1.0f + s4.w) + sh4.w;
    ((float4*)(out + (size_t)row * NDIM))[tid] = o;
    split_store4(oh, ol, (size_t)row * NDIM + tid * 4, o);
}

// ---------------- plain LN ----------------
__global__ __launch_bounds__(256) void lnbase_kernel(
    const float* __restrict__ a, const float* __restrict__ addb,
    float* __restrict__ out, float eps)
{
    int row = blockIdx.x, tid = threadIdx.x;
    float4 v = ((const float4*)(a + (size_t)row * NDIM))[tid];
    if (addb) {
        float4 w = ((const float4*)(addb + (size_t)row * NDIM))[tid];
        v.x += w.x; v.y += w.y; v.z += w.z; v.w += w.w;
    }
    float sum = block_sum_256(v.x + v.y + v.z + v.w);
    float mean = sum * (1.0f / NDIM);
    float dx = v.x - mean, dy = v.y - mean, dz = v.z - mean, dw = v.w - mean;
    float sq = block_sum_256(dx * dx + dy * dy + dz * dz + dw * dw);
    float r = rsqrtf(sq * (1.0f / NDIM) + eps);
    ((float4*)(out + (size_t)row * NDIM))[tid] = make_float4(dx * r, dy * r, dz * r, dw * r);
}

// ---------------- affine -> hi/lo ----------------
__global__ void affine_kernel(const float* __restrict__ x, const float* __restrict__ g,
                              const float* __restrict__ bsh,
                              __nv_bfloat16* __restrict__ oh, __nv_bfloat16* __restrict__ ol, int n4)
{
    int idx = blockIdx.x * blockDim.x + threadIdx.x;
    if (idx >= n4) return;
    int c = (idx & 255) << 2;
    float4 xv = ((const float4*)x)[idx];
    float4 gv = *(const float4*)(g + c);
    float4 bv = *(const float4*)(bsh + c);
    split_store4(oh, ol, (size_t)idx * 4,
                 make_float4(xv.x * gv.x + bv.x, xv.y * gv.y + bv.y,
                             xv.z * gv.z + bv.z, xv.w * gv.w + bv.w));
}

// ---------------- silu -> hi/lo ----------------
__global__ void silu_kernel(const float* __restrict__ x,
                            __nv_bfloat16* __restrict__ oh, __nv_bfloat16* __restrict__ ol, int n4)
{
    int idx = blockIdx.x * blockDim.x + threadIdx.x;
    if (idx >= n4) return;
    float4 v = ((const float4*)x)[idx];
    split_store4(oh, ol, (size_t)idx * 4,
                 make_float4(v.x / (1.0f + expf(-v.x)), v.y / (1.0f + expf(-v.y)),
                             v.z / (1.0f + expf(-v.z)), v.w / (1.0f + expf(-v.w))));
}

// ---------------- split only ----------------
__global__ void split_kernel(const float* __restrict__ x,
                             __nv_bfloat16* __restrict__ oh, __nv_bfloat16* __restrict__ ol, int n4)
{
    int idx = blockIdx.x * blockDim.x + threadIdx.x;
    if (idx >= n4) return;
    split_store4(oh, ol, (size_t)idx * 4, ((const float4*)x)[idx]);
}

// ---------------- (1+alpha)*q2 + x ----------------
__global__ void combine_kernel(const float* __restrict__ al, const float* __restrict__ q2,
                               const float* __restrict__ x, float* __restrict__ out, int n4)
{
    int idx = blockIdx.x * blockDim.x + threadIdx.x;
    if (idx >= n4) return;
    float4 a = ((const float4*)al)[idx];
    float4 q = ((const float4*)q2)[idx];
    float4 v = ((const float4*)x)[idx];
    ((float4*)out)[idx] = make_float4((1.0f + a.x) * q.x + v.x, (1.0f + a.y) * q.y + v.y,
                                      (1.0f + a.z) * q.z + v.z, (1.0f + a.w) * q.w + v.w);
}

// ================= driver =================
extern "C" void kernel_launch(void* const* d_in, const int* in_sizes, int n_in,
                              void* d_out, int out_size)
{
    const float* in_q   = (const float*)d_in[0];
    const float* in_c   = (const float*)d_in[1];
    const float* in_pe  = (const float*)d_in[2];
    const float* mod_w  = (const float*)d_in[3];
    const float* mod_b  = (const float*)d_in[4];
    const float* sa_qw  = (const float*)d_in[5];
    const float* sa_kw  = (const float*)d_in[6];
    const float* sa_vw  = (const float*)d_in[7];
    const float* sa_pw  = (const float*)d_in[8];
    const float* sa_pb  = (const float*)d_in[9];
    const float* ca_qw  = (const float*)d_in[10];
    const float* ca_kw  = (const float*)d_in[11];
    const float* ca_vw  = (const float*)d_in[12];
    const float* ca_pw  = (const float*)d_in[13];
    const float* ca_pb  = (const float*)d_in[14];
    const float* nk_g   = (const float*)d_in[15];
    const float* nk_b   = (const float*)d_in[16];
    const float* nv_g   = (const float*)d_in[17];
    const float* nv_b   = (const float*)d_in[18];
    const float* al_w   = (const float*)d_in[19];
    const float* al_b   = (const float*)d_in[20];
    const float* fc1_w  = (const float*)d_in[21];
    const float* fc1_b  = (const float*)d_in[22];
    const float* fc2_w  = (const float*)d_in[23];
    const float* fc2_b  = (const float*)d_in[24];
    const float* head_w = (const float*)d_in[25];
    const float* head_b = (const float*)d_in[26];
    const int*   pm     = (const int*)d_in[27];
    float* out = (float*)d_out;

    static bool attr_done = false;
    if (!attr_done) {
        cudaFuncSetAttribute(mm_gemm_kernel, cudaFuncAttributeMaxDynamicSharedMemorySize, GEMM_SMEM);
        attr_done = true;
    }

    float *x, *x2, *qh, *kh, *vh, *q2b, *al, *mod, *lncpe, *lnc;
    cudaGetSymbolAddress((void**)&x,     g_x);
    cudaGetSymbolAddress((void**)&x2,    g_x2);
    cudaGetSymbolAddress((void**)&qh,    g_qh);
    cudaGetSymbolAddress((void**)&kh,    g_kh);
    cudaGetSymbolAddress((void**)&vh,    g_vh);
    cudaGetSymbolAddress((void**)&q2b,   g_q2b);
    cudaGetSymbolAddress((void**)&al,    g_alpha);
    cudaGetSymbolAddress((void**)&mod,   g_mod);
    cudaGetSymbolAddress((void**)&lncpe, g_lncpe);
    cudaGetSymbolAddress((void**)&lnc,   g_lnc);

    __nv_bfloat16 *whi, *wlo, *xh, *xl, *ath, *atl, *q2h, *q2l,
                  *kih, *kil, *vih, *vil, *sch, *scl, *hbh, *hbl;
    cudaGetSymbolAddress((void**)&whi, g_whi);
    cudaGetSymbolAddress((void**)&wlo, g_wlo);
    cudaGetSymbolAddress((void**)&xh,  g_xh);
    cudaGetSymbolAddress((void**)&xl,  g_xl);
    cudaGetSymbolAddress((void**)&ath, g_ath);
    cudaGetSymbolAddress((void**)&atl, g_atl);
    cudaGetSymbolAddress((void**)&q2h, g_q2h);
    cudaGetSymbolAddress((void**)&q2l, g_q2l);
    cudaGetSymbolAddress((void**)&kih, g_kih);
    cudaGetSymbolAddress((void**)&kil, g_kil);
    cudaGetSymbolAddress((void**)&vih, g_vih);
    cudaGetSymbolAddress((void**)&vil, g_vil);
    cudaGetSymbolAddress((void**)&sch, g_sch);
    cudaGetSymbolAddress((void**)&scl, g_scl);
    cudaGetSymbolAddress((void**)&hbh, g_hbh);
    cudaGetSymbolAddress((void**)&hbl, g_hbl);

    const size_t DD = (size_t)NDIM * NDIM;
    const int nC4 = MC * NDIM / 4;
    const int nQ4 = MQ * NDIM / 4;

    // ---- weight prep (batched over layers) ----
    wprep(mod_w, whi + OFF_MOD, wlo + OFF_MOD, NDIM, 6 * NDIM, (size_t)NDIM * 6 * NDIM, WPL);
    wprep(sa_qw, whi + OFF_SAQ, wlo + OFF_SAQ, NDIM, NDIM, DD, WPL);
    wprep(sa_kw, whi + OFF_SAK, wlo + OFF_SAK, NDIM, NDIM, DD, WPL);
    wprep(sa_vw, whi + OFF_SAV, wlo + OFF_SAV, NDIM, NDIM, DD, WPL);
    wprep(sa_pw, whi + OFF_SAP, wlo + OFF_SAP, NDIM, NDIM, DD, WPL);
    wprep(ca_qw, whi + OFF_CAQ, wlo + OFF_CAQ, NDIM, NDIM, DD, WPL);
    wprep(ca_kw, whi + OFF_CAK, wlo + OFF_CAK, NDIM, NDIM, DD, WPL);
    wprep(ca_vw, whi + OFF_CAV, wlo + OFF_CAV, NDIM, NDIM, DD, WPL);
    wprep(ca_pw, whi + OFF_CAP, wlo + OFF_CAP, NDIM, NDIM, DD, WPL);
    wprep(al_w,      whi + OFF_AL0, wlo + OFF_AL0, NDIM, NDIM, 2 * DD, WPL);
    wprep(al_w + DD, whi + OFF_AL1, wlo + OFF_AL1, NDIM, NDIM, 2 * DD, WPL);
    wprep(fc1_w, whi + OFF_FC1, wlo + OFF_FC1, NDIM, NHID, (size_t)NDIM * NHID, WPL);
    wprep(fc2_w, whi + OFF_FC2, wlo + OFF_FC2, NHID, NDIM, (size_t)NHID * NDIM, WPL);

    // ---- init ----
    cudaMemcpyAsync(x, in_q, sizeof(float) * (size_t)MQ * NDIM, cudaMemcpyDeviceToDevice);
    split_kernel<<<(nQ4 + 255) / 256, 256>>>(in_q, xh, xl, nQ4);
    silu_kernel<<<(nC4 + 255) / 256, 256>>>(in_c, sch, scl, nC4);
    lnbase_kernel<<<MC, 256>>>(in_c, in_pe, lncpe, 1e-5f);
    lnbase_kernel<<<MC, 256>>>(in_c, nullptr, lnc, 1e-5f);

    for (int l = 0; l < NL; l++) {
        const __nv_bfloat16* H = whi + (size_t)l * WPL;
        const __nv_bfloat16* L = wlo + (size_t)l * WPL;

        // AdaLN modulation
        tcg(sch, scl, H + OFF_MOD, L + OFF_MOD, mod_b + (size_t)l * 6 * NDIM,
            nullptr, mod, nullptr, nullptr, MC, 6 * NDIM, NDIM, 0);

        // ---- self-attention ----
        tcg(xh, xl, H + OFF_SAQ, L + OFF_SAQ, nullptr, nullptr, qh, nullptr, nullptr, MQ, NDIM, NDIM, 0);
        tcg(xh, xl, H + OFF_SAK, L + OFF_SAK, nullptr, nullptr, kh, nullptr, nullptr, MQ, NDIM, NDIM, 0);
        tcg(xh, xl, H + OFF_SAV, L + OFF_SAV, nullptr, nullptr, vh, nullptr, nullptr, MQ, NDIM, NDIM, 0);
        attn_kernel<true, NTOK><<<dim3(NH, NB), 256>>>(qh, kh, vh, pm, ath, atl);
        tcg(ath, atl, H + OFF_SAP, L + OFF_SAP, sa_pb + (size_t)l * NDIM,
            x, x2, nullptr, nullptr, MQ, NDIM, NDIM, 0);
        modln_kernel<<<MQ, 256>>>(x2, mod, x, xh, xl, 0);

        // ---- cross-attention ----
        affine_kernel<<<(nC4 + 255) / 256, 256>>>(lncpe, nk_g + (size_t)l * NDIM,
                                                  nk_b + (size_t)l * NDIM, kih, kil, nC4);
        affine_kernel<<<(nC4 + 255) / 256, 256>>>(lnc, nv_g + (size_t)l * NDIM,
                                                  nv_b + (size_t)l * NDIM, vih, vil, nC4);
        tcg(xh, xl,   H + OFF_CAQ, L + OFF_CAQ, nullptr, nullptr, qh, nullptr, nullptr, MQ, NDIM, NDIM, 0);
        tcg(kih, kil, H + OFF_CAK, L + OFF_CAK, nullptr, nullptr, kh, nullptr, nullptr, MC, NDIM, NDIM, 0);
        tcg(vih, vil, H + OFF_CAV, L + OFF_CAV, nullptr, nullptr, vh, nullptr, nullptr, MC, NDIM, NDIM, 0);
        attn_kernel<false, NS><<<dim3(NH, NB), 256>>>(qh, kh, vh, pm, ath, atl);
        tcg(ath, atl, H + OFF_CAP, L + OFF_CAP, ca_pb + (size_t)l * NDIM,
            nullptr, q2b, q2h, q2l, MQ, NDIM, NDIM, 0);
        // alpha = q2 @ al_w[0:D] + x @ al_w[D:2D] + al_b
        tcg(xh, xl,   H + OFF_AL1, L + OFF_AL1, al_b + (size_t)l * NDIM,
            nullptr, al, nullptr, nullptr, MQ, NDIM, NDIM, 0);
        tcg(q2h, q2l, H + OFF_AL0, L + OFF_AL0, nullptr,
            al, al, nullptr, nullptr, MQ, NDIM, NDIM, 0);
        combine_kernel<<<(nQ4 + 255) / 256, 256>>>(al, q2b, x, x2, nQ4);
        modln_kernel<<<MQ, 256>>>(x2, mod, x, xh, xl, 1);

        // ---- MLP ----
        tcg(xh, xl, H + OFF_FC1, L + OFF_FC1, fc1_b + (size_t)l * NHID,
            nullptr, nullptr, hbh, hbl, MQ, NHID, NDIM, 1 /*gelu*/);
        tcg(hbh, hbl, H + OFF_FC2, L + OFF_FC2, fc2_b + (size_t)l * NDIM,
            x, x2, nullptr, nullptr, MQ, NDIM, NHID, 0);
        modln_kernel<<<MQ, 256>>>(x2, mod, x, xh, xl, 2);
    }

    // head (fp32, tiny N)
    dim3 hgrid((NV + 127) / 128, (MQ + 127) / 128);
    sgemm_kernel<<<hgrid, 256>>>(x, head_w, head_b, out, MQ, NV, NDIM);
}

// round 10
// speedup vs baseline: 1.3098x; 1.3098x over previous
#include <cuda_runtime.h>
#include <cuda_fp16.h>
#include <math.h>
#include <stdint.h>

// ---------------- problem constants ----------------
#define NB   32
#define NS   128
#define NDIM 1024
#define NH   16
#define HD   64
#define NL   6
#define NV   18
#define NTOK 256
#define NHID 4096
#define NEGV (-10000.0f)

#define MQ (NB * NTOK)     // 8192
#define MC (NB * NS)       // 4096

// ---------------- weight pool layout (fp16, transposed [N,K]) ----------------
#define OFF_MOD 0ULL
#define OFF_SAQ 6291456ULL
#define OFF_SAK 7340032ULL
#define OFF_SAV 8388608ULL
#define OFF_SAP 9437184ULL
#define OFF_CAQ 10485760ULL
#define OFF_CAK 11534336ULL
#define OFF_CAV 12582912ULL
#define OFF_CAP 13631488ULL
#define OFF_AL0 14680064ULL
#define OFF_AL1 15728640ULL
#define OFF_FC1 16777216ULL
#define OFF_FC2 20971520ULL
#define WPL     25165824ULL
#define WTOT    (6ULL * WPL)

// ---------------- scratch (device globals) ----------------
__device__ float g_x    [(size_t)MQ * NDIM];
__device__ float g_x2   [(size_t)MQ * NDIM];
__device__ float g_qh   [(size_t)MQ * NDIM];
__device__ float g_kh   [(size_t)MQ * NDIM];
__device__ float g_vh   [(size_t)MQ * NDIM];
__device__ float g_q2b  [(size_t)MQ * NDIM];
__device__ float g_alpha[(size_t)MQ * NDIM];
__device__ float g_mod  [(size_t)MC * 6 * NDIM];
__device__ float g_lncpe[(size_t)MC * NDIM];
__device__ float g_lnc  [(size_t)MC * NDIM];

__device__ __half g_wh [WTOT];
__device__ __half g_xh [(size_t)MQ * NDIM];
__device__ __half g_xl [(size_t)MQ * NDIM];
__device__ __half g_ath[(size_t)MQ * NDIM];
__device__ __half g_atl[(size_t)MQ * NDIM];
__device__ __half g_q2h[(size_t)MQ * NDIM];
__device__ __half g_q2l[(size_t)MQ * NDIM];
__device__ __half g_kih[(size_t)MC * NDIM];
__device__ __half g_kil[(size_t)MC * NDIM];
__device__ __half g_vih[(size_t)MC * NDIM];
__device__ __half g_vil[(size_t)MC * NDIM];
__device__ __half g_sch[(size_t)MC * NDIM];
__device__ __half g_scl[(size_t)MC * NDIM];
__device__ __half g_hbh[(size_t)MQ * NHID];
__device__ __half g_hbl[(size_t)MQ * NHID];

// ================= portable PTX helpers =================
__device__ __forceinline__ uint32_t smem_to_u32(const void* p) {
    uint32_t a;
    asm("{ .reg .u64 t; cvta.to.shared.u64 t, %1; cvt.u32.u64 %0, t; }" : "=r"(a) : "l"(p));
    return a;
}
__device__ __forceinline__ void cpa16(uint32_t dst, const void* src) {
    asm volatile("cp.async.cg.shared.global [%0], [%1], 16;" :: "r"(dst), "l"(src) : "memory");
}
#define CP_COMMIT() asm volatile("cp.async.commit_group;" ::: "memory")
template <int N> __device__ __forceinline__ void cp_wait() {
    asm volatile("cp.async.wait_group %0;" :: "n"(N) : "memory");
}
__device__ __forceinline__ void ldsm4(uint32_t* r, uint32_t addr) {
    asm volatile("ldmatrix.sync.aligned.m8n8.x4.shared.b16 {%0,%1,%2,%3}, [%4];"
                 : "=r"(r[0]), "=r"(r[1]), "=r"(r[2]), "=r"(r[3]) : "r"(addr));
}
__device__ __forceinline__ void mma16816(float* c, const uint32_t* a, const uint32_t* b) {
    asm volatile("mma.sync.aligned.m16n8k16.row.col.f32.f16.f16.f32 "
                 "{%0,%1,%2,%3}, {%4,%5,%6,%7}, {%8,%9}, {%0,%1,%2,%3};"
                 : "+f"(c[0]), "+f"(c[1]), "+f"(c[2]), "+f"(c[3])
                 : "r"(a[0]), "r"(a[1]), "r"(a[2]), "r"(a[3]), "r"(b[0]), "r"(b[1]));
}

// smem geometry: 3 tiles (Ah,Al,B) of 128 rows x 32 fp16, row stride 80B (conflict-free)
#define TILE_BYTES 10240            // 128 * 80
#define STAGE_BYTES 30720           // 3 tiles
#define NSTAGE 4
#define GEMM_SMEM (NSTAGE * STAGE_BYTES)   // 122880

// ---------------- hi/lo split store helpers ----------------
__device__ __forceinline__ void split_store4(__half* hp, __half* lp, size_t idx, float4 v) {
    __half h[4], lo[4];
    float f[4] = {v.x, v.y, v.z, v.w};
    #pragma unroll
    for (int u = 0; u < 4; u++) {
        h[u]  = __float2half_rn(f[u]);
        lo[u] = __float2half_rn(f[u] - __half2float(h[u]));
    }
    *reinterpret_cast<uint2*>(hp + idx) = *reinterpret_cast<uint2*>(h);
    *reinterpret_cast<uint2*>(lp + idx) = *reinterpret_cast<uint2*>(lo);
}
__device__ __forceinline__ void split_store2(__half* hp, __half* lp,
                                             size_t idx, float v0, float v1) {
    __half h[2], lo[2];
    h[0] = __float2half_rn(v0); lo[0] = __float2half_rn(v0 - __half2float(h[0]));
    h[1] = __float2half_rn(v1); lo[1] = __float2half_rn(v1 - __half2float(h[1]));
    *reinterpret_cast<uint32_t*>(hp + idx) = *reinterpret_cast<uint32_t*>(h);
    *reinterpret_cast<uint32_t*>(lp + idx) = *reinterpret_cast<uint32_t*>(lo);
}

// ================= mma.sync split-fp16 GEMM (2 products: Ah*B + Al*B) =================
// C[M,N] = act((Ah+Al)@Bt + bias) + res, Bt [N,K] fp16.
__global__ __launch_bounds__(256, 1) void mm_gemm_kernel(
    const __half* __restrict__ Ah, const __half* __restrict__ Al,
    const __half* __restrict__ B,
    const float* __restrict__ bias, const float* __restrict__ res,
    float* __restrict__ C, __half* __restrict__ Ch, __half* __restrict__ Cl,
    int M, int N, int K, int act)
{
    extern __shared__ char smem[];
    const uint32_t sb = smem_to_u32(smem);
    const int tid  = threadIdx.x;
    const int lane = tid & 31;
    const int wid  = tid >> 5;
    const int wm   = wid & 3;     // warp m index (0..3), 32 rows each
    const int wn   = wid >> 2;    // warp n index (0..1), 64 cols each
    const int bm = blockIdx.y * 128;
    const int bn = blockIdx.x * 128;

    float acc[2][8][4];
    #pragma unroll
    for (int mt = 0; mt < 2; mt++)
        #pragma unroll
        for (int nt = 0; nt < 8; nt++)
            #pragma unroll
            for (int u = 0; u < 4; u++) acc[mt][nt][u] = 0.0f;

    uint32_t a_off[2];
    #pragma unroll
    for (int mt = 0; mt < 2; mt++)
        a_off[mt] = (uint32_t)((wm * 32 + mt * 16 + (lane & 15)) * 80 + ((lane >> 4) << 4));
    const int g = lane >> 3;
    uint32_t b_off[4];
    #pragma unroll
    for (int p = 0; p < 4; p++)
        b_off[p] = (uint32_t)((wn * 64 + p * 16 + ((g >> 1) << 3) + (lane & 7)) * 80
                              + ((g & 1) << 4));

    const int NIT = K >> 5;       // BK = 32

    auto load_stage = [&](int it, int s) {
        const int k0 = it << 5;
        const uint32_t sbase = sb + (uint32_t)s * STAGE_BYTES;
        const __half* gsrc[3] = {
            Ah + (size_t)bm * K + k0, Al + (size_t)bm * K + k0,
            B  + (size_t)bn * K + k0 };
        #pragma unroll
        for (int t = 0; t < 3; t++) {
            #pragma unroll
            for (int u = 0; u < 2; u++) {
                const int q   = tid + u * 256;     // 0..511
                const int row = q >> 2, c = q & 3;
                cpa16(sbase + (uint32_t)t * TILE_BYTES + row * 80 + c * 16,
                      gsrc[t] + (size_t)row * K + c * 8);
            }
        }
        CP_COMMIT();
    };

    #pragma unroll
    for (int p = 0; p < NSTAGE - 1; p++) load_stage(p, p);

    for (int it = 0; it < NIT; it++) {
        const int s = it & (NSTAGE - 1);
        if (it + NSTAGE - 1 < NIT) {
            cp_wait<NSTAGE - 2>();
            __syncthreads();
            load_stage(it + NSTAGE - 1, (it + NSTAGE - 1) & (NSTAGE - 1));
        } else if (it + NSTAGE - 1 == NIT) {
            cp_wait<0>();
            __syncthreads();
        }

        const uint32_t sbase = sb + (uint32_t)s * STAGE_BYTES;
        #pragma unroll
        for (int ks = 0; ks < 2; ks++) {
            const uint32_t kb = (uint32_t)(ks << 5);
            uint32_t fah[2][4], fal[2][4], fb[8][2];
            #pragma unroll
            for (int mt = 0; mt < 2; mt++) {
                ldsm4(fah[mt], sbase + a_off[mt] + kb);
                ldsm4(fal[mt], sbase + TILE_BYTES + a_off[mt] + kb);
            }
            #pragma unroll
            for (int p = 0; p < 4; p++) {
                uint32_t t4[4];
                ldsm4(t4, sbase + 2 * TILE_BYTES + b_off[p] + kb);
                fb[2 * p][0] = t4[0]; fb[2 * p][1] = t4[1];
                fb[2 * p + 1][0] = t4[2]; fb[2 * p + 1][1] = t4[3];
            }
            #pragma unroll
            for (int mt = 0; mt < 2; mt++)
                #pragma unroll
                for (int nt = 0; nt < 8; nt++) {
                    mma16816(acc[mt][nt], fah[mt], fb[nt]);
                    mma16816(acc[mt][nt], fal[mt], fb[nt]);
                }
        }
    }

    // epilogue
    const int cn0 = (lane & 3) << 1;
    #pragma unroll
    for (int mt = 0; mt < 2; mt++) {
        #pragma unroll
        for (int nt = 0; nt < 8; nt++) {
            const int gn = bn + wn * 64 + nt * 8 + cn0;
            #pragma unroll
            for (int half_ = 0; half_ < 2; half_++) {
                const int gm = bm + wm * 32 + mt * 16 + (lane >> 2) + half_ * 8;
                float v0 = acc[mt][nt][half_ * 2];
                float v1 = acc[mt][nt][half_ * 2 + 1];
                if (bias) { v0 += bias[gn]; v1 += bias[gn + 1]; }
                if (act) {
                    v0 = 0.5f * v0 * (1.0f + erff(v0 * 0.70710678118654752f));
                    v1 = 0.5f * v1 * (1.0f + erff(v1 * 0.70710678118654752f));
                }
                const size_t oidx = (size_t)gm * N + gn;
                if (res) { v0 += res[oidx]; v1 += res[oidx + 1]; }
                if (C) { C[oidx] = v0; C[oidx + 1] = v1; }
                if (Ch) split_store2(Ch, Cl, oidx, v0, v1);
            }
        }
    }
}

static inline void tcg(const __half* Ah, const __half* Al, const __half* B,
                       const float* bias, const float* res, float* C,
                       __half* Ch, __half* Cl, int M, int N, int K, int act) {
    dim3 grid(N / 128, M / 128);
    mm_gemm_kernel<<<grid, 256, GEMM_SMEM>>>(Ah, Al, B, bias, res, C, Ch, Cl, M, N, K, act);
}

// ================= batched weight prep: W[K,N] fp32 -> Wt fp16 [N,K] =================
__global__ void wprep_kernel(const float* __restrict__ W, __half* __restrict__ H,
                             int K, int N, size_t src_stride, size_t dst_stride) {
    __shared__ float t[32][33];
    const size_t lyr = blockIdx.z;
    W += lyr * src_stride;
    H += lyr * dst_stride;
    const int bx = blockIdx.x * 32, by = blockIdx.y * 32;
    const int tx = threadIdx.x, ty = threadIdx.y;
    #pragma unroll
    for (int i = 0; i < 32; i += 8)
        t[ty + i][tx] = W[(size_t)(by + ty + i) * N + bx + tx];
    __syncthreads();
    #pragma unroll
    for (int i = 0; i < 32; i += 8) {
        const int n = bx + ty + i, k = by + tx;
        H[(size_t)n * K + k] = __float2half_rn(t[tx][ty + i]);
    }
}
static inline void wprep(const float* W, __half* H, int K, int N, size_t sstr, size_t dstr) {
    wprep_kernel<<<dim3(N / 32, K / 32, NL), dim3(32, 8)>>>(W, H, K, N, sstr, dstr);
}

// ---------------- block reduction ----------------
__device__ __forceinline__ float block_sum_256(float v) {
    __shared__ float sbuf[8];
    int tid = threadIdx.x;
    #pragma unroll
    for (int o = 16; o > 0; o >>= 1) v += __shfl_xor_sync(0xffffffffu, v, o);
    if ((tid & 31) == 0) sbuf[tid >> 5] = v;
    __syncthreads();
    float r = 0.0f;
    if (tid < 32) {
        r = (tid < 8) ? sbuf[tid] : 0.0f;
        #pragma unroll
        for (int o = 4; o > 0; o >>= 1) r += __shfl_xor_sync(0xffffffffu, r, o);
        if (tid == 0) sbuf[0] = r;
    }
    __syncthreads();
    r = sbuf[0];
    __syncthreads();
    return r;
}

// ---------------- fp32 SGEMM (head only, N=18) ----------------
__global__ __launch_bounds__(256) void sgemm_kernel(
    const float* __restrict__ A, const float* __restrict__ B,
    const float* __restrict__ bias, float* __restrict__ C, int M, int N, int K)
{
    __shared__ float As[16][128];
    __shared__ float Bs[16][128];
    const int bm = blockIdx.y * 128, bn = blockIdx.x * 128;
    const int tid = threadIdx.x;
    const int ty = tid >> 4, tx = tid & 15;
    const int arow = tid >> 2, acol = (tid & 3) << 2;
    const int brow = tid >> 5, bcol = (tid & 31) << 2;
    float acc[8][8];
    #pragma unroll
    for (int i = 0; i < 8; i++)
        #pragma unroll
        for (int j = 0; j < 8; j++) acc[i][j] = 0.0f;
    for (int k0 = 0; k0 < K; k0 += 16) {
        #pragma unroll
        for (int r = 0; r < 2; r++) {
            int row = arow + r * 64, gm = bm + row;
            float4 v = make_float4(0.f, 0.f, 0.f, 0.f);
            if (gm < M) v = *(const float4*)(A + (size_t)gm * K + k0 + acol);
            As[acol][row] = v.x; As[acol + 1][row] = v.y;
            As[acol + 2][row] = v.z; As[acol + 3][row] = v.w;
        }
        #pragma unroll
        for (int r = 0; r < 2; r++) {
            int row = brow + r * 8, gk = k0 + row, gn = bn + bcol;
            float4 v = make_float4(0.f, 0.f, 0.f, 0.f);
            const float* bp = B + (size_t)gk * N + gn;
            if (gn < N)     v.x = bp[0];
            if (gn + 1 < N) v.y = bp[1];
            if (gn + 2 < N) v.z = bp[2];
            if (gn + 3 < N) v.w = bp[3];
            *(float4*)&Bs[row][bcol] = v;
        }
        __syncthreads();
        #pragma unroll
        for (int k = 0; k < 16; k++) {
            float4 a0 = *(const float4*)&As[k][ty * 8];
            float4 a1 = *(const float4*)&As[k][ty * 8 + 4];
            float4 b0 = *(const float4*)&Bs[k][tx * 8];
            float4 b1 = *(const float4*)&Bs[k][tx * 8 + 4];
            float av[8] = {a0.x, a0.y, a0.z, a0.w, a1.x, a1.y, a1.z, a1.w};
            float bv[8] = {b0.x, b0.y, b0.z, b0.w, b1.x, b1.y, b1.z, b1.w};
            #pragma unroll
            for (int i = 0; i < 8; i++)
                #pragma unroll
                for (int j = 0; j < 8; j++) acc[i][j] += av[i] * bv[j];
        }
        __syncthreads();
    }
    #pragma unroll
    for (int i = 0; i < 8; i++) {
        int m = bm + ty * 8 + i;
        if (m >= M) continue;
        #pragma unroll
        for (int j = 0; j < 8; j++) {
            int n = bn + tx * 8 + j;
            if (n < N) C[(size_t)m * N + n] = acc[i][j] + (bias ? bias[n] : 0.0f);
        }
    }
}

// ---------------- fused attention: 2 queries per thread-pair, d-split ----------------
template<bool SELF, int KTOK>
__global__ __launch_bounds__(256, 1) void attn_kernel(
    const float* __restrict__ Q, const float* __restrict__ K,
    const float* __restrict__ V, const int* __restrict__ pm,
    __half* __restrict__ Oh, __half* __restrict__ Ol)
{
    __shared__ float ks[64][64];
    __shared__ float vs[64][64];
    __shared__ float pmb[KTOK];
    const int h = blockIdx.x, b = blockIdx.y;
    const int tid  = threadIdx.x;
    const int unit = tid >> 1;
    const int half_ = tid & 1;
    const int dbase = half_ * 32;
    const unsigned pmask = 3u << (tid & 30);

    if (tid < KTOK) {
        int ct = SELF ? (tid >> 1) : tid;
        pmb[tid] = (float)pm[b * NS + ct] * NEGV;
    }

    float qr[2][32], acc[2][32];
    #pragma unroll
    for (int qi = 0; qi < 2; qi++) {
        const float* qp = Q + ((size_t)(b * NTOK + unit * 2 + qi) * NDIM + h * HD + dbase);
        #pragma unroll
        for (int d = 0; d < 32; d += 4) {
            float4 t = *(const float4*)(qp + d);
            qr[qi][d] = t.x; qr[qi][d + 1] = t.y; qr[qi][d + 2] = t.z; qr[qi][d + 3] = t.w;
            acc[qi][d] = 0.f; acc[qi][d + 1] = 0.f; acc[qi][d + 2] = 0.f; acc[qi][d + 3] = 0.f;
        }
    }

    float m0 = -INFINITY, m1 = -INFINITY, l0 = 0.f, l1 = 0.f;
    const int jmax0 = SELF ? (unit * 2)     : unit;
    const int jmax1 = SELF ? (unit * 2 + 1) : unit;

    for (int c0 = 0; c0 < KTOK; c0 += 64) {
        __syncthreads();
        #pragma unroll
        for (int u = 0; u < 4; u++) {
            int lin = tid + u * 256;
            int row = lin >> 4, c4 = (lin & 15) << 2;
            size_t gidx = (size_t)(b * KTOK + c0 + row) * NDIM + h * HD + c4;
            *(float4*)&ks[row][c4] = *(const float4*)(K + gidx);
            *(float4*)&vs[row][c4] = *(const float4*)(V + gidx);
        }
        __syncthreads();
        int jend = jmax1 - c0; if (jend > 63) jend = 63;
        for (int j = 0; j <= jend; j++) {
            float d0 = 0.f, d1 = 0.f;
            #pragma unroll
            for (int d = 0; d < 32; d += 4) {
                float4 kk = *(const float4*)&ks[j][dbase + d];
                d0 += qr[0][d] * kk.x + qr[0][d + 1] * kk.y + qr[0][d + 2] * kk.z + qr[0][d + 3] * kk.w;
                d1 += qr[1][d] * kk.x + qr[1][d + 1] * kk.y + qr[1][d + 2] * kk.z + qr[1][d + 3] * kk.w;
            }
            d0 += __shfl_xor_sync(pmask, d0, 1);
            d1 += __shfl_xor_sync(pmask, d1, 1);
            const float pb = pmb[c0 + j];
            float s1 = d1 * 0.125f + pb;
            float nm1 = fmaxf(m1, s1);
            float corr1 = __expf(m1 - nm1);
            float p1 = __expf(s1 - nm1);
            m1 = nm1; l1 = l1 * corr1 + p1;
            float p0 = 0.f, corr0 = 1.f;
            if (!SELF || (c0 + j) <= jmax0) {
                float s0 = d0 * 0.125f + pb;
                float nm0 = fmaxf(m0, s0);
                corr0 = __expf(m0 - nm0);
                p0 = __expf(s0 - nm0);
                m0 = nm0; l0 = l0 * corr0 + p0;
            }
            #pragma unroll
            for (int d = 0; d < 32; d += 4) {
                float4 vv = *(const float4*)&vs[j][dbase + d];
                acc[0][d]     = acc[0][d]     * corr0 + p0 * vv.x;
                acc[0][d + 1] = acc[0][d + 1] * corr0 + p0 * vv.y;
                acc[0][d + 2] = acc[0][d + 2] * corr0 + p0 * vv.z;
                acc[0][d + 3] = acc[0][d + 3] * corr0 + p0 * vv.w;
                acc[1][d]     = acc[1][d]     * corr1 + p1 * vv.x;
                acc[1][d + 1] = acc[1][d + 1] * corr1 + p1 * vv.y;
                acc[1][d + 2] = acc[1][d + 2] * corr1 + p1 * vv.z;
                acc[1][d + 3] = acc[1][d + 3] * corr1 + p1 * vv.w;
            }
        }
    }
    const float inv0 = 1.0f / l0, inv1 = 1.0f / l1;
    #pragma unroll
    for (int qi = 0; qi < 2; qi++) {
        const float inv = qi ? inv1 : inv0;
        const size_t off = (size_t)(b * NTOK + unit * 2 + qi) * NDIM + h * HD + dbase;
        #pragma unroll
        for (int d = 0; d < 32; d += 4)
            split_store4(Oh, Ol, off + d,
                         make_float4(acc[qi][d] * inv, acc[qi][d + 1] * inv,
                                     acc[qi][d + 2] * inv, acc[qi][d + 3] * inv));
    }
}

// ---------------- modulated LN -> fp32 x + hi/lo split ----------------
__global__ __launch_bounds__(256) void modln_kernel(
    const float* __restrict__ x, const float* __restrict__ mod,
    float* __restrict__ out, __half* __restrict__ oh, __half* __restrict__ ol, int stage)
{
    int row = blockIdx.x, tid = threadIdx.x;
    int b = row / NTOK, n = row % NTOK, ct = n >> 1;
    float4 v = ((const float4*)(x + (size_t)row * NDIM))[tid];
    float sum = block_sum_256(v.x + v.y + v.z + v.w);
    float mean = sum * (1.0f / NDIM);
    float dx = v.x - mean, dy = v.y - mean, dz = v.z - mean, dw = v.w - mean;
    float sq = block_sum_256(dx * dx + dy * dy + dz * dz + dw * dw);
    float r = rsqrtf(sq * (1.0f / NDIM) + 1e-6f);
    const float* mp = mod + (size_t)(b * NS + ct) * (6 * NDIM) + (size_t)(2 * stage) * NDIM;
    float4 s4  = *(const float4*)(mp + tid * 4);
    float4 sh4 = *(const float4*)(mp + NDIM + tid * 4);
    float4 o;
    o.x = dx * r * (1.0f + s4.x) + sh4.x;
    o.y = dy * r * (1.0f + s4.y) + sh4.y;
    o.z = dz * r * (1.0f + s4.z) + sh4.z;
    o.w = dw * r * (1.0f + s4.w) + sh4.w;
    ((float4*)(out + (size_t)row * NDIM))[tid] = o;
    split_store4(oh, ol, (size_t)row * NDIM + tid * 4, o);
}

// ---------------- plain LN ----------------
__global__ __launch_bounds__(256) void lnbase_kernel(
    const float* __restrict__ a, const float* __restrict__ addb,
    float* __restrict__ out, float eps)
{
    int row = blockIdx.x, tid = threadIdx.x;
    float4 v = ((const float4*)(a + (size_t)row * NDIM))[tid];
    if (addb) {
        float4 w = ((const float4*)(addb + (size_t)row * NDIM))[tid];
        v.x += w.x; v.y += w.y; v.z += w.z; v.w += w.w;
    }
    float sum = block_sum_256(v.x + v.y + v.z + v.w);
    float mean = sum * (1.0f / NDIM);
    float dx = v.x - mean, dy = v.y - mean, dz = v.z - mean, dw = v.w - mean;
    float sq = block_sum_256(dx * dx + dy * dy + dz * dz + dw * dw);
    float r = rsqrtf(sq * (1.0f / NDIM) + eps);
    ((float4*)(out + (size_t)row * NDIM))[tid] = make_float4(dx * r, dy * r, dz * r, dw * r);
}

// ---------------- affine -> hi/lo ----------------
__global__ void affine_kernel(const float* __restrict__ x, const float* __restrict__ g,
                              const float* __restrict__ bsh,
                              __half* __restrict__ oh, __half* __restrict__ ol, int n4)
{
    int idx = blockIdx.x * blockDim.x + threadIdx.x;
    if (idx >= n4) return;
    int c = (idx & 255) << 2;
    float4 xv = ((const float4*)x)[idx];
    float4 gv = *(const float4*)(g + c);
    float4 bv = *(const float4*)(bsh + c);
    split_store4(oh, ol, (size_t)idx * 4,
                 make_float4(xv.x * gv.x + bv.x, xv.y * gv.y + bv.y,
                             xv.z * gv.z + bv.z, xv.w * gv.w + bv.w));
}

// ---------------- silu -> hi/lo ----------------
__global__ void silu_kernel(const float* __restrict__ x,
                            __half* __restrict__ oh, __half* __restrict__ ol, int n4)
{
    int idx = blockIdx.x * blockDim.x + threadIdx.x;
    if (idx >= n4) return;
    float4 v = ((const float4*)x)[idx];
    split_store4(oh, ol, (size_t)idx * 4,
                 make_float4(v.x / (1.0f + expf(-v.x)), v.y / (1.0f + expf(-v.y)),
                             v.z / (1.0f + expf(-v.z)), v.w / (1.0f + expf(-v.w))));
}

// ---------------- split only ----------------
__global__ void split_kernel(const float* __restrict__ x,
                             __half* __restrict__ oh, __half* __restrict__ ol, int n4)
{
    int idx = blockIdx.x * blockDim.x + threadIdx.x;
    if (idx >= n4) return;
    split_store4(oh, ol, (size_t)idx * 4, ((const float4*)x)[idx]);
}

// ---------------- (1+alpha)*q2 + x ----------------
__global__ void combine_kernel(const float* __restrict__ al, const float* __restrict__ q2,
                               const float* __restrict__ x, float* __restrict__ out, int n4)
{
    int idx = blockIdx.x * blockDim.x + threadIdx.x;
    if (idx >= n4) return;
    float4 a = ((const float4*)al)[idx];
    float4 q = ((const float4*)q2)[idx];
    float4 v = ((const float4*)x)[idx];
    ((float4*)out)[idx] = make_float4((1.0f + a.x) * q.x + v.x, (1.0f + a.y) * q.y + v.y,
                                      (1.0f + a.z) * q.z + v.z, (1.0f + a.w) * q.w + v.w);
}

// ================= driver =================
extern "C" void kernel_launch(void* const* d_in, const int* in_sizes, int n_in,
                              void* d_out, int out_size)
{
    const float* in_q   = (const float*)d_in[0];
    const float* in_c   = (const float*)d_in[1];
    const float* in_pe  = (const float*)d_in[2];
    const float* mod_w  = (const float*)d_in[3];
    const float* mod_b  = (const float*)d_in[4];
    const float* sa_qw  = (const float*)d_in[5];
    const float* sa_kw  = (const float*)d_in[6];
    const float* sa_vw  = (const float*)d_in[7];
    const float* sa_pw  = (const float*)d_in[8];
    const float* sa_pb  = (const float*)d_in[9];
    const float* ca_qw  = (const float*)d_in[10];
    const float* ca_kw  = (const float*)d_in[11];
    const float* ca_vw  = (const float*)d_in[12];
    const float* ca_pw  = (const float*)d_in[13];
    const float* ca_pb  = (const float*)d_in[14];
    const float* nk_g   = (const float*)d_in[15];
    const float* nk_b   = (const float*)d_in[16];
    const float* nv_g   = (const float*)d_in[17];
    const float* nv_b   = (const float*)d_in[18];
    const float* al_w   = (const float*)d_in[19];
    const float* al_b   = (const float*)d_in[20];
    const float* fc1_w  = (const float*)d_in[21];
    const float* fc1_b  = (const float*)d_in[22];
    const float* fc2_w  = (const float*)d_in[23];
    const float* fc2_b  = (const float*)d_in[24];
    const float* head_w = (const float*)d_in[25];
    const float* head_b = (const float*)d_in[26];
    const int*   pm     = (const int*)d_in[27];
    float* out = (float*)d_out;

    static bool attr_done = false;
    if (!attr_done) {
        cudaFuncSetAttribute(mm_gemm_kernel, cudaFuncAttributeMaxDynamicSharedMemorySize, GEMM_SMEM);
        attr_done = true;
    }

    float *x, *x2, *qh, *kh, *vh, *q2b, *al, *mod, *lncpe, *lnc;
    cudaGetSymbolAddress((void**)&x,     g_x);
    cudaGetSymbolAddress((void**)&x2,    g_x2);
    cudaGetSymbolAddress((void**)&qh,    g_qh);
    cudaGetSymbolAddress((void**)&kh,    g_kh);
    cudaGetSymbolAddress((void**)&vh,    g_vh);
    cudaGetSymbolAddress((void**)&q2b,   g_q2b);
    cudaGetSymbolAddress((void**)&al,    g_alpha);
    cudaGetSymbolAddress((void**)&mod,   g_mod);
    cudaGetSymbolAddress((void**)&lncpe, g_lncpe);
    cudaGetSymbolAddress((void**)&lnc,   g_lnc);

    __half *wh, *xh, *xl, *ath, *atl, *q2h, *q2l,
           *kih, *kil, *vih, *vil, *sch, *scl, *hbh, *hbl;
    cudaGetSymbolAddress((void**)&wh,  g_wh);
    cudaGetSymbolAddress((void**)&xh,  g_xh);
    cudaGetSymbolAddress((void**)&xl,  g_xl);
    cudaGetSymbolAddress((void**)&ath, g_ath);
    cudaGetSymbolAddress((void**)&atl, g_atl);
    cudaGetSymbolAddress((void**)&q2h, g_q2h);
    cudaGetSymbolAddress((void**)&q2l, g_q2l);
    cudaGetSymbolAddress((void**)&kih, g_kih);
    cudaGetSymbolAddress((void**)&kil, g_kil);
    cudaGetSymbolAddress((void**)&vih, g_vih);
    cudaGetSymbolAddress((void**)&vil, g_vil);
    cudaGetSymbolAddress((void**)&sch, g_sch);
    cudaGetSymbolAddress((void**)&scl, g_scl);
    cudaGetSymbolAddress((void**)&hbh, g_hbh);
    cudaGetSymbolAddress((void**)&hbl, g_hbl);

    const size_t DD = (size_t)NDIM * NDIM;
    const int nC4 = MC * NDIM / 4;
    const int nQ4 = MQ * NDIM / 4;

    // ---- weight prep (batched over layers, fp16) ----
    wprep(mod_w, wh + OFF_MOD, NDIM, 6 * NDIM, (size_t)NDIM * 6 * NDIM, WPL);
    wprep(sa_qw, wh + OFF_SAQ, NDIM, NDIM, DD, WPL);
    wprep(sa_kw, wh + OFF_SAK, NDIM, NDIM, DD, WPL);
    wprep(sa_vw, wh + OFF_SAV, NDIM, NDIM, DD, WPL);
    wprep(sa_pw, wh + OFF_SAP, NDIM, NDIM, DD, WPL);
    wprep(ca_qw, wh + OFF_CAQ, NDIM, NDIM, DD, WPL);
    wprep(ca_kw, wh + OFF_CAK, NDIM, NDIM, DD, WPL);
    wprep(ca_vw, wh + OFF_CAV, NDIM, NDIM, DD, WPL);
    wprep(ca_pw, wh + OFF_CAP, NDIM, NDIM, DD, WPL);
    wprep(al_w,      wh + OFF_AL0, NDIM, NDIM, 2 * DD, WPL);
    wprep(al_w + DD, wh + OFF_AL1, NDIM, NDIM, 2 * DD, WPL);
    wprep(fc1_w, wh + OFF_FC1, NDIM, NHID, (size_t)NDIM * NHID, WPL);
    wprep(fc2_w, wh + OFF_FC2, NHID, NDIM, (size_t)NHID * NDIM, WPL);

    // ---- init ----
    cudaMemcpyAsync(x, in_q, sizeof(float) * (size_t)MQ * NDIM, cudaMemcpyDeviceToDevice);
    split_kernel<<<(nQ4 + 255) / 256, 256>>>(in_q, xh, xl, nQ4);
    silu_kernel<<<(nC4 + 255) / 256, 256>>>(in_c, sch, scl, nC4);
    lnbase_kernel<<<MC, 256>>>(in_c, in_pe, lncpe, 1e-5f);
    lnbase_kernel<<<MC, 256>>>(in_c, nullptr, lnc, 1e-5f);

    for (int l = 0; l < NL; l++) {
        const __half* H = wh + (size_t)l * WPL;

        // AdaLN modulation
        tcg(sch, scl, H + OFF_MOD, mod_b + (size_t)l * 6 * NDIM,
            nullptr, mod, nullptr, nullptr, MC, 6 * NDIM, NDIM, 0);

        // ---- self-attention ----
        tcg(xh, xl, H + OFF_SAQ, nullptr, nullptr, qh, nullptr, nullptr, MQ, NDIM, NDIM, 0);
        tcg(xh, xl, H + OFF_SAK, nullptr, nullptr, kh, nullptr, nullptr, MQ, NDIM, NDIM, 0);
        tcg(xh, xl, H + OFF_SAV, nullptr, nullptr, vh, nullptr, nullptr, MQ, NDIM, NDIM, 0);
        attn_kernel<true, NTOK><<<dim3(NH, NB), 256>>>(qh, kh, vh, pm, ath, atl);
        tcg(ath, atl, H + OFF_SAP, sa_pb + (size_t)l * NDIM,
            x, x2, nullptr, nullptr, MQ, NDIM, NDIM, 0);
        modln_kernel<<<MQ, 256>>>(x2, mod, x, xh, xl, 0);

        // ---- cross-attention ----
        affine_kernel<<<(nC4 + 255) / 256, 256>>>(lncpe, nk_g + (size_t)l * NDIM,
                                                  nk_b + (size_t)l * NDIM, kih, kil, nC4);
        affine_kernel<<<(nC4 + 255) / 256, 256>>>(lnc, nv_g + (size_t)l * NDIM,
                                                  nv_b + (size_t)l * NDIM, vih, vil, nC4);
        tcg(xh, xl,   H + OFF_CAQ, nullptr, nullptr, qh, nullptr, nullptr, MQ, NDIM, NDIM, 0);
        tcg(kih, kil, H + OFF_CAK, nullptr, nullptr, kh, nullptr, nullptr, MC, NDIM, NDIM, 0);
        tcg(vih, vil, H + OFF_CAV, nullptr, nullptr, vh, nullptr, nullptr, MC, NDIM, NDIM, 0);
        attn_kernel<false, NS><<<dim3(NH, NB), 256>>>(qh, kh, vh, pm, ath, atl);
        tcg(ath, atl, H + OFF_CAP, ca_pb + (size_t)l * NDIM,
            nullptr, q2b, q2h, q2l, MQ, NDIM, NDIM, 0);
        // alpha = q2 @ al_w[0:D] + x @ al_w[D:2D] + al_b
        tcg(xh, xl,   H + OFF_AL1, al_b + (size_t)l * NDIM,
            nullptr, al, nullptr, nullptr, MQ, NDIM, NDIM, 0);
        tcg(q2h, q2l, H + OFF_AL0, nullptr, al, al, nullptr, nullptr, MQ, NDIM, NDIM, 0);
        combine_kernel<<<(nQ4 + 255) / 256, 256>>>(al, q2b, x, x2, nQ4);
        modln_kernel<<<MQ, 256>>>(x2, mod, x, xh, xl, 1);

        // ---- MLP ----
        tcg(xh, xl, H + OFF_FC1, fc1_b + (size_t)l * NHID,
            nullptr, nullptr, hbh, hbl, MQ, NHID, NDIM, 1 /*gelu*/);
        tcg(hbh, hbl, H + OFF_FC2, fc2_b + (size_t)l * NDIM,
            x, x2, nullptr, nullptr, MQ, NDIM, NHID, 0);
        modln_kernel<<<MQ, 256>>>(x2, mod, x, xh, xl, 2);
    }

    // head (fp32, tiny N)
    dim3 hgrid((NV + 127) / 128, (MQ + 127) / 128);
    sgemm_kernel<<<hgrid, 256>>>(x, head_w, head_b, out, MQ, NV, NDIM);
}

// round 15
// speedup vs baseline: 1.4759x; 1.1268x over previous
#include <cuda_runtime.h>
#include <cuda_fp16.h>
#include <math.h>
#include <stdint.h>

// ---------------- problem constants ----------------
#define NB   32
#define NS   128
#define NDIM 1024
#define NH   16
#define HD   64
#define NL   6
#define NV   18
#define NTOK 256
#define NHID 4096
#define NEGV (-10000.0f)

#define MQ (NB * NTOK)     // 8192
#define MC (NB * NS)       // 4096

// ---------------- weight pool layout (fp16, transposed [N,K]) ----------------
#define OFF_MOD 0ULL
#define OFF_SAQ 6291456ULL
#define OFF_SAK 7340032ULL
#define OFF_SAV 8388608ULL
#define OFF_SAP 9437184ULL
#define OFF_CAQ 10485760ULL
#define OFF_CAK 11534336ULL
#define OFF_CAV 12582912ULL
#define OFF_CAP 13631488ULL
#define OFF_AL0 14680064ULL
#define OFF_AL1 15728640ULL
#define OFF_FC1 16777216ULL
#define OFF_FC2 20971520ULL
#define WPL     25165824ULL
#define WTOT    (6ULL * WPL)

// ---------------- scratch (device globals) ----------------
__device__ float g_x    [(size_t)MQ * NDIM];
__device__ float g_x2   [(size_t)MQ * NDIM];
__device__ float g_qh   [(size_t)MQ * NDIM];
__device__ float g_kh   [(size_t)MQ * NDIM];
__device__ float g_vh   [(size_t)MQ * NDIM];
__device__ float g_q2b  [(size_t)MQ * NDIM];
__device__ float g_alpha[(size_t)MQ * NDIM];
__device__ float g_mod  [(size_t)MC * 6 * NDIM];
__device__ float g_lncpe[(size_t)MC * NDIM];
__device__ float g_lnc  [(size_t)MC * NDIM];

__device__ __half g_wh [WTOT];
__device__ __half g_xh [(size_t)MQ * NDIM];
__device__ __half g_xl [(size_t)MQ * NDIM];
__device__ __half g_ath[(size_t)MQ * NDIM];
__device__ __half g_atl[(size_t)MQ * NDIM];
__device__ __half g_q2h[(size_t)MQ * NDIM];
__device__ __half g_q2l[(size_t)MQ * NDIM];
__device__ __half g_kih[(size_t)MC * NDIM];
__device__ __half g_kil[(size_t)MC * NDIM];
__device__ __half g_vih[(size_t)MC * NDIM];
__device__ __half g_vil[(size_t)MC * NDIM];
__device__ __half g_sch[(size_t)MC * NDIM];
__device__ __half g_scl[(size_t)MC * NDIM];
__device__ __half g_hbh[(size_t)MQ * NHID];
__device__ __half g_hbl[(size_t)MQ * NHID];

// ================= portable PTX helpers =================
__device__ __forceinline__ uint32_t smem_to_u32(const void* p) {
    uint32_t a;
    asm("{ .reg .u64 t; cvta.to.shared.u64 t, %1; cvt.u32.u64 %0, t; }" : "=r"(a) : "l"(p));
    return a;
}
__device__ __forceinline__ void cpa16(uint32_t dst, const void* src) {
    asm volatile("cp.async.cg.shared.global [%0], [%1], 16;" :: "r"(dst), "l"(src) : "memory");
}
#define CP_COMMIT() asm volatile("cp.async.commit_group;" ::: "memory")
template <int N> __device__ __forceinline__ void cp_wait() {
    asm volatile("cp.async.wait_group %0;" :: "n"(N) : "memory");
}
__device__ __forceinline__ void ldsm4(uint32_t* r, uint32_t addr) {
    asm volatile("ldmatrix.sync.aligned.m8n8.x4.shared.b16 {%0,%1,%2,%3}, [%4];"
                 : "=r"(r[0]), "=r"(r[1]), "=r"(r[2]), "=r"(r[3]) : "r"(addr));
}
__device__ __forceinline__ void mma16816(float* c, const uint32_t* a, const uint32_t* b) {
    asm volatile("mma.sync.aligned.m16n8k16.row.col.f32.f16.f16.f32 "
                 "{%0,%1,%2,%3}, {%4,%5,%6,%7}, {%8,%9}, {%0,%1,%2,%3};"
                 : "+f"(c[0]), "+f"(c[1]), "+f"(c[2]), "+f"(c[3])
                 : "r"(a[0]), "r"(a[1]), "r"(a[2]), "r"(a[3]), "r"(b[0]), "r"(b[1]));
}

// smem geometry: 3 tiles (Ah,Al,B) of 128 rows x 32 fp16, row stride 80B (conflict-free)
#define TILE_BYTES 10240            // 128 * 80
#define STAGE_BYTES 30720           // 3 tiles
#define NSTAGE 3
#define GEMM_SMEM (NSTAGE * STAGE_BYTES)   // 92160  -> 2 CTAs/SM

// ---------------- hi/lo split store helpers ----------------
__device__ __forceinline__ void split_store4(__half* hp, __half* lp, size_t idx, float4 v) {
    __half h[4], lo[4];
    float f[4] = {v.x, v.y, v.z, v.w};
    #pragma unroll
    for (int u = 0; u < 4; u++) {
        h[u]  = __float2half_rn(f[u]);
        lo[u] = __float2half_rn(f[u] - __half2float(h[u]));
    }
    *reinterpret_cast<uint2*>(hp + idx) = *reinterpret_cast<uint2*>(h);
    *reinterpret_cast<uint2*>(lp + idx) = *reinterpret_cast<uint2*>(lo);
}
__device__ __forceinline__ void split_store2(__half* hp, __half* lp,
                                             size_t idx, float v0, float v1) {
    __half h[2], lo[2];
    h[0] = __float2half_rn(v0); lo[0] = __float2half_rn(v0 - __half2float(h[0]));
    h[1] = __float2half_rn(v1); lo[1] = __float2half_rn(v1 - __half2float(h[1]));
    *reinterpret_cast<uint32_t*>(hp + idx) = *reinterpret_cast<uint32_t*>(h);
    *reinterpret_cast<uint32_t*>(lp + idx) = *reinterpret_cast<uint32_t*>(lo);
}

// ================= mma.sync split-fp16 GEMM (2 products, 2 CTAs/SM) =================
// C[M,N] = act((Ah+Al)@Bt + bias) + res, Bt [N,K] fp16.
__global__ __launch_bounds__(256, 2) void mm_gemm_kernel(
    const __half* __restrict__ Ah, const __half* __restrict__ Al,
    const __half* __restrict__ B,
    const float* __restrict__ bias, const float* __restrict__ res,
    float* __restrict__ C, __half* __restrict__ Ch, __half* __restrict__ Cl,
    int M, int N, int K, int act)
{
    extern __shared__ char smem[];
    const uint32_t sb = smem_to_u32(smem);
    const int tid  = threadIdx.x;
    const int lane = tid & 31;
    const int wid  = tid >> 5;
    const int wm   = wid & 3;     // warp m index (0..3), 32 rows each
    const int wn   = wid >> 2;    // warp n index (0..1), 64 cols each
    const int bm = blockIdx.y * 128;
    const int bn = blockIdx.x * 128;

    float acc[2][8][4];
    #pragma unroll
    for (int mt = 0; mt < 2; mt++)
        #pragma unroll
        for (int nt = 0; nt < 8; nt++)
            #pragma unroll
            for (int u = 0; u < 4; u++) acc[mt][nt][u] = 0.0f;

    uint32_t a_off[2];
    #pragma unroll
    for (int mt = 0; mt < 2; mt++)
        a_off[mt] = (uint32_t)((wm * 32 + mt * 16 + (lane & 15)) * 80 + ((lane >> 4) << 4));
    const int g = lane >> 3;
    uint32_t b_off[4];
    #pragma unroll
    for (int p = 0; p < 4; p++)
        b_off[p] = (uint32_t)((wn * 64 + p * 16 + ((g >> 1) << 3) + (lane & 7)) * 80
                              + ((g & 1) << 4));

    const int NIT = K >> 5;       // BK = 32

    auto load_stage = [&](int it, int s) {
        const int k0 = it << 5;
        const uint32_t sbase = sb + (uint32_t)s * STAGE_BYTES;
        const __half* gsrc[3] = {
            Ah + (size_t)bm * K + k0, Al + (size_t)bm * K + k0,
            B  + (size_t)bn * K + k0 };
        #pragma unroll
        for (int t = 0; t < 3; t++) {
            #pragma unroll
            for (int u = 0; u < 2; u++) {
                const int q   = tid + u * 256;     // 0..511
                const int row = q >> 2, c = q & 3;
                cpa16(sbase + (uint32_t)t * TILE_BYTES + row * 80 + c * 16,
                      gsrc[t] + (size_t)row * K + c * 8);
            }
        }
        CP_COMMIT();
    };

    #pragma unroll
    for (int p = 0; p < NSTAGE - 1; p++) load_stage(p, p);

    int s = 0;
    for (int it = 0; it < NIT; it++) {
        if (it + NSTAGE - 1 < NIT) {
            cp_wait<NSTAGE - 2>();
            __syncthreads();
            int ns = s + NSTAGE - 1; if (ns >= NSTAGE) ns -= NSTAGE;
            load_stage(it + NSTAGE - 1, ns);
        } else if (it + NSTAGE - 1 == NIT) {
            cp_wait<0>();
            __syncthreads();
        }

        const uint32_t sbase = sb + (uint32_t)s * STAGE_BYTES;
        #pragma unroll
        for (int ks = 0; ks < 2; ks++) {
            const uint32_t kb = (uint32_t)(ks << 5);
            uint32_t fah[2][4], fal[2][4], fb[8][2];
            #pragma unroll
            for (int mt = 0; mt < 2; mt++) {
                ldsm4(fah[mt], sbase + a_off[mt] + kb);
                ldsm4(fal[mt], sbase + TILE_BYTES + a_off[mt] + kb);
            }
            #pragma unroll
            for (int p = 0; p < 4; p++) {
                uint32_t t4[4];
                ldsm4(t4, sbase + 2 * TILE_BYTES + b_off[p] + kb);
                fb[2 * p][0] = t4[0]; fb[2 * p][1] = t4[1];
                fb[2 * p + 1][0] = t4[2]; fb[2 * p + 1][1] = t4[3];
            }
            #pragma unroll
            for (int mt = 0; mt < 2; mt++)
                #pragma unroll
                for (int nt = 0; nt < 8; nt++) {
                    mma16816(acc[mt][nt], fah[mt], fb[nt]);
                    mma16816(acc[mt][nt], fal[mt], fb[nt]);
                }
        }
        if (++s == NSTAGE) s = 0;
    }

    // epilogue
    const int cn0 = (lane & 3) << 1;
    #pragma unroll
    for (int mt = 0; mt < 2; mt++) {
        #pragma unroll
        for (int nt = 0; nt < 8; nt++) {
            const int gn = bn + wn * 64 + nt * 8 + cn0;
            #pragma unroll
            for (int half_ = 0; half_ < 2; half_++) {
                const int gm = bm + wm * 32 + mt * 16 + (lane >> 2) + half_ * 8;
                float v0 = acc[mt][nt][half_ * 2];
                float v1 = acc[mt][nt][half_ * 2 + 1];
                if (bias) { v0 += bias[gn]; v1 += bias[gn + 1]; }
                if (act) {
                    v0 = 0.5f * v0 * (1.0f + erff(v0 * 0.70710678118654752f));
                    v1 = 0.5f * v1 * (1.0f + erff(v1 * 0.70710678118654752f));
                }
                const size_t oidx = (size_t)gm * N + gn;
                if (res) { v0 += res[oidx]; v1 += res[oidx + 1]; }
                if (C) { C[oidx] = v0; C[oidx + 1] = v1; }
                if (Ch) split_store2(Ch, Cl, oidx, v0, v1);
            }
        }
    }
}

static inline void tcg(const __half* Ah, const __half* Al, const __half* B,
                       const float* bias, const float* res, float* C,
                       __half* Ch, __half* Cl, int M, int N, int K, int act) {
    dim3 grid(N / 128, M / 128);
    mm_gemm_kernel<<<grid, 256, GEMM_SMEM>>>(Ah, Al, B, bias, res, C, Ch, Cl, M, N, K, act);
}

// ================= batched weight prep: W[K,N] fp32 -> Wt fp16 [N,K] =================
__global__ void wprep_kernel(const float* __restrict__ W, __half* __restrict__ H,
                             int K, int N, size_t src_stride, size_t dst_stride) {
    __shared__ float t[32][33];
    const size_t lyr = blockIdx.z;
    W += lyr * src_stride;
    H += lyr * dst_stride;
    const int bx = blockIdx.x * 32, by = blockIdx.y * 32;
    const int tx = threadIdx.x, ty = threadIdx.y;
    #pragma unroll
    for (int i = 0; i < 32; i += 8)
        t[ty + i][tx] = W[(size_t)(by + ty + i) * N + bx + tx];
    __syncthreads();
    #pragma unroll
    for (int i = 0; i < 32; i += 8) {
        const int n = bx + ty + i, k = by + tx;
        H[(size_t)n * K + k] = __float2half_rn(t[tx][ty + i]);
    }
}
static inline void wprep(const float* W, __half* H, int K, int N, size_t sstr, size_t dstr) {
    wprep_kernel<<<dim3(N / 32, K / 32, NL), dim3(32, 8)>>>(W, H, K, N, sstr, dstr);
}

// ---------------- block reduction ----------------
__device__ __forceinline__ float block_sum_256(float v) {
    __shared__ float sbuf[8];
    int tid = threadIdx.x;
    #pragma unroll
    for (int o = 16; o > 0; o >>= 1) v += __shfl_xor_sync(0xffffffffu, v, o);
    if ((tid & 31) == 0) sbuf[tid >> 5] = v;
    __syncthreads();
    float r = 0.0f;
    if (tid < 32) {
        r = (tid < 8) ? sbuf[tid] : 0.0f;
        #pragma unroll
        for (int o = 4; o > 0; o >>= 1) r += __shfl_xor_sync(0xffffffffu, r, o);
        if (tid == 0) sbuf[0] = r;
    }
    __syncthreads();
    r = sbuf[0];
    __syncthreads();
    return r;
}

// ---------------- fp32 SGEMM (head only, N=18) ----------------
__global__ __launch_bounds__(256) void sgemm_kernel(
    const float* __restrict__ A, const float* __restrict__ B,
    const float* __restrict__ bias, float* __restrict__ C, int M, int N, int K)
{
    __shared__ float As[16][128];
    __shared__ float Bs[16][128];
    const int bm = blockIdx.y * 128, bn = blockIdx.x * 128;
    const int tid = threadIdx.x;
    const int ty = tid >> 4, tx = tid & 15;
    const int arow = tid >> 2, acol = (tid & 3) << 2;
    const int brow = tid >> 5, bcol = (tid & 31) << 2;
    float acc[8][8];
    #pragma unroll
    for (int i = 0; i < 8; i++)
        #pragma unroll
        for (int j = 0; j < 8; j++) acc[i][j] = 0.0f;
    for (int k0 = 0; k0 < K; k0 += 16) {
        #pragma unroll
        for (int r = 0; r < 2; r++) {
            int row = arow + r * 64, gm = bm + row;
            float4 v = make_float4(0.f, 0.f, 0.f, 0.f);
            if (gm < M) v = *(const float4*)(A + (size_t)gm * K + k0 + acol);
            As[acol][row] = v.x; As[acol + 1][row] = v.y;
            As[acol + 2][row] = v.z; As[acol + 3][row] = v.w;
        }
        #pragma unroll
        for (int r = 0; r < 2; r++) {
            int row = brow + r * 8, gk = k0 + row, gn = bn + bcol;
            float4 v = make_float4(0.f, 0.f, 0.f, 0.f);
            const float* bp = B + (size_t)gk * N + gn;
            if (gn < N)     v.x = bp[0];
            if (gn + 1 < N) v.y = bp[1];
            if (gn + 2 < N) v.z = bp[2];
            if (gn + 3 < N) v.w = bp[3];
            *(float4*)&Bs[row][bcol] = v;
        }
        __syncthreads();
        #pragma unroll
        for (int k = 0; k < 16; k++) {
            float4 a0 = *(const float4*)&As[k][ty * 8];
            float4 a1 = *(const float4*)&As[k][ty * 8 + 4];
            float4 b0 = *(const float4*)&Bs[k][tx * 8];
            float4 b1 = *(const float4*)&Bs[k][tx * 8 + 4];
            float av[8] = {a0.x, a0.y, a0.z, a0.w, a1.x, a1.y, a1.z, a1.w};
            float bv[8] = {b0.x, b0.y, b0.z, b0.w, b1.x, b1.y, b1.z, b1.w};
            #pragma unroll
            for (int i = 0; i < 8; i++)
                #pragma unroll
                for (int j = 0; j < 8; j++) acc[i][j] += av[i] * bv[j];
        }
        __syncthreads();
    }
    #pragma unroll
    for (int i = 0; i < 8; i++) {
        int m = bm + ty * 8 + i;
        if (m >= M) continue;
        #pragma unroll
        for (int j = 0; j < 8; j++) {
            int n = bn + tx * 8 + j;
            if (n < N) C[(size_t)m * N + n] = acc[i][j] + (bias ? bias[n] : 0.0f);
        }
    }
}

// ---------------- fused attention: 2 queries per thread-pair, d-split ----------------
template<bool SELF, int KTOK>
__global__ __launch_bounds__(256) void attn_kernel(
    const float* __restrict__ Q, const float* __restrict__ K,
    const float* __restrict__ V, const int* __restrict__ pm,
    __half* __restrict__ Oh, __half* __restrict__ Ol)
{
    __shared__ float ks[64][64];
    __shared__ float vs[64][64];
    __shared__ float pmb[KTOK];
    const int h = blockIdx.x, b = blockIdx.y;
    const int tid  = threadIdx.x;
    const int unit = tid >> 1;
    const int half_ = tid & 1;
    const int dbase = half_ * 32;
    const unsigned pmask = 3u << (tid & 30);

    if (tid < KTOK) {
        int ct = SELF ? (tid >> 1) : tid;
        pmb[tid] = (float)pm[b * NS + ct] * NEGV;
    }

    float qr[2][32], acc[2][32];
    #pragma unroll
    for (int qi = 0; qi < 2; qi++) {
        const float* qp = Q + ((size_t)(b * NTOK + unit * 2 + qi) * NDIM + h * HD + dbase);
        #pragma unroll
        for (int d = 0; d < 32; d += 4) {
            float4 t = *(const float4*)(qp + d);
            qr[qi][d] = t.x; qr[qi][d + 1] = t.y; qr[qi][d + 2] = t.z; qr[qi][d + 3] = t.w;
            acc[qi][d] = 0.f; acc[qi][d + 1] = 0.f; acc[qi][d + 2] = 0.f; acc[qi][d + 3] = 0.f;
        }
    }

    float m0 = -INFINITY, m1 = -INFINITY, l0 = 0.f, l1 = 0.f;
    const int jmax0 = SELF ? (unit * 2)     : unit;
    const int jmax1 = SELF ? (unit * 2 + 1) : unit;

    for (int c0 = 0; c0 < KTOK; c0 += 64) {
        __syncthreads();
        #pragma unroll
        for (int u = 0; u < 4; u++) {
            int lin = tid + u * 256;
            int row = lin >> 4, c4 = (lin & 15) << 2;
            size_t gidx = (size_t)(b * KTOK + c0 + row) * NDIM + h * HD + c4;
            *(float4*)&ks[row][c4] = *(const float4*)(K + gidx);
            *(float4*)&vs[row][c4] = *(const float4*)(V + gidx);
        }
        __syncthreads();
        int jend = jmax1 - c0; if (jend > 63) jend = 63;
        for (int j = 0; j <= jend; j++) {
            float d0 = 0.f, d1 = 0.f;
            #pragma unroll
            for (int d = 0; d < 32; d += 4) {
                float4 kk = *(const float4*)&ks[j][dbase + d];
                d0 += qr[0][d] * kk.x + qr[0][d + 1] * kk.y + qr[0][d + 2] * kk.z + qr[0][d + 3] * kk.w;
                d1 += qr[1][d] * kk.x + qr[1][d + 1] * kk.y + qr[1][d + 2] * kk.z + qr[1][d + 3] * kk.w;
            }
            d0 += __shfl_xor_sync(pmask, d0, 1);
            d1 += __shfl_xor_sync(pmask, d1, 1);
            const float pb = pmb[c0 + j];
            float s1 = d1 * 0.125f + pb;
            float nm1 = fmaxf(m1, s1);
            float corr1 = __expf(m1 - nm1);
            float p1 = __expf(s1 - nm1);
            m1 = nm1; l1 = l1 * corr1 + p1;
            float p0 = 0.f, corr0 = 1.f;
            if (!SELF || (c0 + j) <= jmax0) {
                float s0 = d0 * 0.125f + pb;
                float nm0 = fmaxf(m0, s0);
                corr0 = __expf(m0 - nm0);
                p0 = __expf(s0 - nm0);
                m0 = nm0; l0 = l0 * corr0 + p0;
            }
            #pragma unroll
            for (int d = 0; d < 32; d += 4) {
                float4 vv = *(const float4*)&vs[j][dbase + d];
                acc[0][d]     = acc[0][d]     * corr0 + p0 * vv.x;
                acc[0][d + 1] = acc[0][d + 1] * corr0 + p0 * vv.y;
                acc[0][d + 2] = acc[0][d + 2] * corr0 + p0 * vv.z;
                acc[0][d + 3] = acc[0][d + 3] * corr0 + p0 * vv.w;
                acc[1][d]     = acc[1][d]     * corr1 + p1 * vv.x;
                acc[1][d + 1] = acc[1][d + 1] * corr1 + p1 * vv.y;
                acc[1][d + 2] = acc[1][d + 2] * corr1 + p1 * vv.z;
                acc[1][d + 3] = acc[1][d + 3] * corr1 + p1 * vv.w;
            }
        }
    }
    const float inv0 = 1.0f / l0, inv1 = 1.0f / l1;
    #pragma unroll
    for (int qi = 0; qi < 2; qi++) {
        const float inv = qi ? inv1 : inv0;
        const size_t off = (size_t)(b * NTOK + unit * 2 + qi) * NDIM + h * HD + dbase;
        #pragma unroll
        for (int d = 0; d < 32; d += 4)
            split_store4(Oh, Ol, off + d,
                         make_float4(acc[qi][d] * inv, acc[qi][d + 1] * inv,
                                     acc[qi][d + 2] * inv, acc[qi][d + 3] * inv));
    }
}

// ---------------- modulated LN -> fp32 x + hi/lo split ----------------
__global__ __launch_bounds__(256) void modln_kernel(
    const float* __restrict__ x, const float* __restrict__ mod,
    float* __restrict__ out, __half* __restrict__ oh, __half* __restrict__ ol, int stage)
{
    int row = blockIdx.x, tid = threadIdx.x;
    int b = row / NTOK, n = row % NTOK, ct = n >> 1;
    float4 v = ((const float4*)(x + (size_t)row * NDIM))[tid];
    float sum = block_sum_256(v.x + v.y + v.z + v.w);
    float mean = sum * (1.0f / NDIM);
    float dx = v.x - mean, dy = v.y - mean, dz = v.z - mean, dw = v.w - mean;
    float sq = block_sum_256(dx * dx + dy * dy + dz * dz + dw * dw);
    float r = rsqrtf(sq * (1.0f / NDIM) + 1e-6f);
    const float* mp = mod + (size_t)(b * NS + ct) * (6 * NDIM) + (size_t)(2 * stage) * NDIM;
    float4 s4  = *(const float4*)(mp + tid * 4);
    float4 sh4 = *(const float4*)(mp + NDIM + tid * 4);
    float4 o;
    o.x = dx * r * (1.0f + s4.x) + sh4.x;
    o.y = dy * r * (1.0f + s4.y) + sh4.y;
    o.z = dz * r * (1.0f + s4.z) + sh4.z;
    o.w = dw * r * (1.0f + s4.w) + sh4.w;
    ((float4*)(out + (size_t)row * NDIM))[tid] = o;
    split_store4(oh, ol, (size_t)row * NDIM + tid * 4, o);
}

// ---------------- plain LN ----------------
__global__ __launch_bounds__(256) void lnbase_kernel(
    const float* __restrict__ a, const float* __restrict__ addb,
    float* __restrict__ out, float eps)
{
    int row = blockIdx.x, tid = threadIdx.x;
    float4 v = ((const float4*)(a + (size_t)row * NDIM))[tid];
    if (addb) {
        float4 w = ((const float4*)(addb + (size_t)row * NDIM))[tid];
        v.x += w.x; v.y += w.y; v.z += w.z; v.w += w.w;
    }
    float sum = block_sum_256(v.x + v.y + v.z + v.w);
    float mean = sum * (1.0f / NDIM);
    float dx = v.x - mean, dy = v.y - mean, dz = v.z - mean, dw = v.w - mean;
    float sq = block_sum_256(dx * dx + dy * dy + dz * dz + dw * dw);
    float r = rsqrtf(sq * (1.0f / NDIM) + eps);
    ((float4*)(out + (size_t)row * NDIM))[tid] = make_float4(dx * r, dy * r, dz * r, dw * r);
}

// ---------------- affine -> hi/lo ----------------
__global__ void affine_kernel(const float* __restrict__ x, const float* __restrict__ g,
                              const float* __restrict__ bsh,
                              __half* __restrict__ oh, __half* __restrict__ ol, int n4)
{
    int idx = blockIdx.x * blockDim.x + threadIdx.x;
    if (idx >= n4) return;
    int c = (idx & 255) << 2;
    float4 xv = ((const float4*)x)[idx];
    float4 gv = *(const float4*)(g + c);
    float4 bv = *(const float4*)(bsh + c);
    split_store4(oh, ol, (size_t)idx * 4,
                 make_float4(xv.x * gv.x + bv.x, xv.y * gv.y + bv.y,
                             xv.z * gv.z + bv.z, xv.w * gv.w + bv.w));
}

// ---------------- silu -> hi/lo ----------------
__global__ void silu_kernel(const float* __restrict__ x,
                            __half* __restrict__ oh, __half* __restrict__ ol, int n4)
{
    int idx = blockIdx.x * blockDim.x + threadIdx.x;
    if (idx >= n4) return;
    float4 v = ((const float4*)x)[idx];
    split_store4(oh, ol, (size_t)idx * 4,
                 make_float4(v.x / (1.0f + expf(-v.x)), v.y / (1.0f + expf(-v.y)),
                             v.z / (1.0f + expf(-v.z)), v.w / (1.0f + expf(-v.w))));
}

// ---------------- split only ----------------
__global__ void split_kernel(const float* __restrict__ x,
                             __half* __restrict__ oh, __half* __restrict__ ol, int n4)
{
    int idx = blockIdx.x * blockDim.x + threadIdx.x;
    if (idx >= n4) return;
    split_store4(oh, ol, (size_t)idx * 4, ((const float4*)x)[idx]);
}

// ---------------- (1+alpha)*q2 + x ----------------
__global__ void combine_kernel(const float* __restrict__ al, const float* __restrict__ q2,
                               const float* __restrict__ x, float* __restrict__ out, int n4)
{
    int idx = blockIdx.x * blockDim.x + threadIdx.x;
    if (idx >= n4) return;
    float4 a = ((const float4*)al)[idx];
    float4 q = ((const float4*)q2)[idx];
    float4 v = ((const float4*)x)[idx];
    ((float4*)out)[idx] = make_float4((1.0f + a.x) * q.x + v.x, (1.0f + a.y) * q.y + v.y,
                                      (1.0f + a.z) * q.z + v.z, (1.0f + a.w) * q.w + v.w);
}

// ================= driver =================
extern "C" void kernel_launch(void* const* d_in, const int* in_sizes, int n_in,
                              void* d_out, int out_size)
{
    const float* in_q   = (const float*)d_in[0];
    const float* in_c   = (const float*)d_in[1];
    const float* in_pe  = (const float*)d_in[2];
    const float* mod_w  = (const float*)d_in[3];
    const float* mod_b  = (const float*)d_in[4];
    const float* sa_qw  = (const float*)d_in[5];
    const float* sa_kw  = (const float*)d_in[6];
    const float* sa_vw  = (const float*)d_in[7];
    const float* sa_pw  = (const float*)d_in[8];
    const float* sa_pb  = (const float*)d_in[9];
    const float* ca_qw  = (const float*)d_in[10];
    const float* ca_kw  = (const float*)d_in[11];
    const float* ca_vw  = (const float*)d_in[12];
    const float* ca_pw  = (const float*)d_in[13];
    const float* ca_pb  = (const float*)d_in[14];
    const float* nk_g   = (const float*)d_in[15];
    const float* nk_b   = (const float*)d_in[16];
    const float* nv_g   = (const float*)d_in[17];
    const float* nv_b   = (const float*)d_in[18];
    const float* al_w   = (const float*)d_in[19];
    const float* al_b   = (const float*)d_in[20];
    const float* fc1_w  = (const float*)d_in[21];
    const float* fc1_b  = (const float*)d_in[22];
    const float* fc2_w  = (const float*)d_in[23];
    const float* fc2_b  = (const float*)d_in[24];
    const float* head_w = (const float*)d_in[25];
    const float* head_b = (const float*)d_in[26];
    const int*   pm     = (const int*)d_in[27];
    float* out = (float*)d_out;

    cudaFuncSetAttribute(mm_gemm_kernel, cudaFuncAttributeMaxDynamicSharedMemorySize, GEMM_SMEM);

    float *x, *x2, *qh, *kh, *vh, *q2b, *al, *mod, *lncpe, *lnc;
    cudaGetSymbolAddress((void**)&x,     g_x);
    cudaGetSymbolAddress((void**)&x2,    g_x2);
    cudaGetSymbolAddress((void**)&qh,    g_qh);
    cudaGetSymbolAddress((void**)&kh,    g_kh);
    cudaGetSymbolAddress((void**)&vh,    g_vh);
    cudaGetSymbolAddress((void**)&q2b,   g_q2b);
    cudaGetSymbolAddress((void**)&al,    g_alpha);
    cudaGetSymbolAddress((void**)&mod,   g_mod);
    cudaGetSymbolAddress((void**)&lncpe, g_lncpe);
    cudaGetSymbolAddress((void**)&lnc,   g_lnc);

    __half *wh, *xh, *xl, *ath, *atl, *q2h, *q2l,
           *kih, *kil, *vih, *vil, *sch, *scl, *hbh, *hbl;
    cudaGetSymbolAddress((void**)&wh,  g_wh);
    cudaGetSymbolAddress((void**)&xh,  g_xh);
    cudaGetSymbolAddress((void**)&xl,  g_xl);
    cudaGetSymbolAddress((void**)&ath, g_ath);
    cudaGetSymbolAddress((void**)&atl, g_atl);
    cudaGetSymbolAddress((void**)&q2h, g_q2h);
    cudaGetSymbolAddress((void**)&q2l, g_q2l);
    cudaGetSymbolAddress((void**)&kih, g_kih);
    cudaGetSymbolAddress((void**)&kil, g_kil);
    cudaGetSymbolAddress((void**)&vih, g_vih);
    cudaGetSymbolAddress((void**)&vil, g_vil);
    cudaGetSymbolAddress((void**)&sch, g_sch);
    cudaGetSymbolAddress((void**)&scl, g_scl);
    cudaGetSymbolAddress((void**)&hbh, g_hbh);
    cudaGetSymbolAddress((void**)&hbl, g_hbl);

    const size_t DD = (size_t)NDIM * NDIM;
    const int nC4 = MC * NDIM / 4;
    const int nQ4 = MQ * NDIM / 4;

    // ---- weight prep (batched over layers, fp16) ----
    wprep(mod_w, wh + OFF_MOD, NDIM, 6 * NDIM, (size_t)NDIM * 6 * NDIM, WPL);
    wprep(sa_qw, wh + OFF_SAQ, NDIM, NDIM, DD, WPL);
    wprep(sa_kw, wh + OFF_SAK, NDIM, NDIM, DD, WPL);
    wprep(sa_vw, wh + OFF_SAV, NDIM, NDIM, DD, WPL);
    wprep(sa_pw, wh + OFF_SAP, NDIM, NDIM, DD, WPL);
    wprep(ca_qw, wh + OFF_CAQ, NDIM, NDIM, DD, WPL);
    wprep(ca_kw, wh + OFF_CAK, NDIM, NDIM, DD, WPL);
    wprep(ca_vw, wh + OFF_CAV, NDIM, NDIM, DD, WPL);
    wprep(ca_pw, wh + OFF_CAP, NDIM, NDIM, DD, WPL);
    wprep(al_w,      wh + OFF_AL0, NDIM, NDIM, 2 * DD, WPL);
    wprep(al_w + DD, wh + OFF_AL1, NDIM, NDIM, 2 * DD, WPL);
    wprep(fc1_w, wh + OFF_FC1, NDIM, NHID, (size_t)NDIM * NHID, WPL);
    wprep(fc2_w, wh + OFF_FC2, NHID, NDIM, (size_t)NHID * NDIM, WPL);

    // ---- init ----
    cudaMemcpyAsync(x, in_q, sizeof(float) * (size_t)MQ * NDIM, cudaMemcpyDeviceToDevice);
    split_kernel<<<(nQ4 + 255) / 256, 256>>>(in_q, xh, xl, nQ4);
    silu_kernel<<<(nC4 + 255) / 256, 256>>>(in_c, sch, scl, nC4);
    lnbase_kernel<<<MC, 256>>>(in_c, in_pe, lncpe, 1e-5f);
    lnbase_kernel<<<MC, 256>>>(in_c, nullptr, lnc, 1e-5f);

    for (int l = 0; l < NL; l++) {
        const __half* H = wh + (size_t)l * WPL;

        // AdaLN modulation
        tcg(sch, scl, H + OFF_MOD, mod_b + (size_t)l * 6 * NDIM,
            nullptr, mod, nullptr, nullptr, MC, 6 * NDIM, NDIM, 0);

        // ---- self-attention ----
        tcg(xh, xl, H + OFF_SAQ, nullptr, nullptr, qh, nullptr, nullptr, MQ, NDIM, NDIM, 0);
        tcg(xh, xl, H + OFF_SAK, nullptr, nullptr, kh, nullptr, nullptr, MQ, NDIM, NDIM, 0);
        tcg(xh, xl, H + OFF_SAV, nullptr, nullptr, vh, nullptr, nullptr, MQ, NDIM, NDIM, 0);
        attn_kernel<true, NTOK><<<dim3(NH, NB), 256>>>(qh, kh, vh, pm, ath, atl);
        tcg(ath, atl, H + OFF_SAP, sa_pb + (size_t)l * NDIM,
            x, x2, nullptr, nullptr, MQ, NDIM, NDIM, 0);
        modln_kernel<<<MQ, 256>>>(x2, mod, x, xh, xl, 0);

        // ---- cross-attention ----
        affine_kernel<<<(nC4 + 255) / 256, 256>>>(lncpe, nk_g + (size_t)l * NDIM,
                                                  nk_b + (size_t)l * NDIM, kih, kil, nC4);
        affine_kernel<<<(nC4 + 255) / 256, 256>>>(lnc, nv_g + (size_t)l * NDIM,
                                                  nv_b + (size_t)l * NDIM, vih, vil, nC4);
        tcg(xh, xl,   H + OFF_CAQ, nullptr, nullptr, qh, nullptr, nullptr, MQ, NDIM, NDIM, 0);
        tcg(kih, kil, H + OFF_CAK, nullptr, nullptr, kh, nullptr, nullptr, MC, NDIM, NDIM, 0);
        tcg(vih, vil, H + OFF_CAV, nullptr, nullptr, vh, nullptr, nullptr, MC, NDIM, NDIM, 0);
        attn_kernel<false, NS><<<dim3(NH, NB), 256>>>(qh, kh, vh, pm, ath, atl);
        tcg(ath, atl, H + OFF_CAP, ca_pb + (size_t)l * NDIM,
            nullptr, q2b, q2h, q2l, MQ, NDIM, NDIM, 0);
        // alpha = q2 @ al_w[0:D] + x @ al_w[D:2D] + al_b
        tcg(xh, xl,   H + OFF_AL1, al_b + (size_t)l * NDIM,
            nullptr, al, nullptr, nullptr, MQ, NDIM, NDIM, 0);
        tcg(q2h, q2l, H + OFF_AL0, nullptr, al, al, nullptr, nullptr, MQ, NDIM, NDIM, 0);
        combine_kernel<<<(nQ4 + 255) / 256, 256>>>(al, q2b, x, x2, nQ4);
        modln_kernel<<<MQ, 256>>>(x2, mod, x, xh, xl, 1);

        // ---- MLP ----
        tcg(xh, xl, H + OFF_FC1, fc1_b + (size_t)l * NHID,
            nullptr, nullptr, hbh, hbl, MQ, NHID, NDIM, 1 /*gelu*/);
        tcg(hbh, hbl, H + OFF_FC2, fc2_b + (size_t)l * NDIM,
            x, x2, nullptr, nullptr, MQ, NDIM, NHID, 0);
        modln_kernel<<<MQ, 256>>>(x2, mod, x, xh, xl, 2);
    }

    // head (fp32, tiny N)
    dim3 hgrid((NV + 127) / 128, (MQ + 127) / 128);
    sgemm_kernel<<<hgrid, 256>>>(x, head_w, head_b, out, MQ, NV, NDIM);
}